// round 6
// baseline (speedup 1.0000x reference)
#include <cuda_runtime.h>
#include <cuda_fp16.h>
#include <cstdint>
#include <math.h>

// ---------------------------------------------------------------------------
// Problem constants
// ---------------------------------------------------------------------------
namespace {
constexpr int N_Q   = 20000;
constexpr int S_SUP = 20000;
constexpr int NEI   = 30;
constexpr int KP    = 15;
constexpr int CIN_  = 128;
constexpr int COUT_ = 256;
constexpr float INV_EXT = 20.0f;

constexpr int M_PAD = 20096;        // 157*128

// Extended-K layout: per k: 4 q-groups of 72 slots
//   j<32: x part; j in [32,68): 36 al channels; j=68: validity; j>68: pad
constexpr int QW    = 72;
constexpr int KROW  = 4 * QW;             // 288
constexpr int BIGK2 = KP * KROW;          // 4320

// GEMM tiling
constexpr int BM = 128, BN = 128, BK = 32;
constexpr int NKC = BIGK2 / BK;           // 135
constexpr int LDS_ = 40;                  // smem row stride (fp16 elems)
constexpr int MAT_BYTES = 128 * LDS_ * 2; // 10240
constexpr int BUF_BYTES = 2 * MAT_BYTES;  // A|B = 20480
constexpr int SMEM_DYN  = 2 * BUF_BYTES;  // 40960 double-buffered
}

// ---------------------------------------------------------------------------
// Scratch (device globals, zero-initialized; pad rows never written)
// ---------------------------------------------------------------------------
__device__ __half g_A[(size_t)M_PAD * BIGK2];
__device__ __half g_B[(size_t)COUT_ * BIGK2];   // [co][kidx]

// ---------------------------------------------------------------------------
// PTX helpers (sm_80+ baseline; legal on family target)
// ---------------------------------------------------------------------------
__device__ __forceinline__ uint32_t smem_u32(const void* p) {
    uint32_t a;
    asm("{ .reg .u64 t; cvta.to.shared.u64 t, %1; cvt.u32.u64 %0, t; }"
        : "=r"(a) : "l"(p));
    return a;
}
__device__ __forceinline__ void cp16(uint32_t s, const void* g) {
    asm volatile("cp.async.cg.shared.global [%0], [%1], 16;" :: "r"(s), "l"(g));
}
__device__ __forceinline__ void cp_commit() {
    asm volatile("cp.async.commit_group;");
}
__device__ __forceinline__ void cp_wait1() {
    asm volatile("cp.async.wait_group 1;" ::: "memory");
}
__device__ __forceinline__ void cp_wait0() {
    asm volatile("cp.async.wait_group 0;" ::: "memory");
}
__device__ __forceinline__ void ldmx4(uint32_t addr, uint32_t* r) {
    asm volatile("ldmatrix.sync.aligned.m8n8.x4.shared.b16 {%0,%1,%2,%3}, [%4];"
                 : "=r"(r[0]), "=r"(r[1]), "=r"(r[2]), "=r"(r[3]) : "r"(addr));
}
__device__ __forceinline__ void ldmx2(uint32_t addr, uint32_t* r) {
    asm volatile("ldmatrix.sync.aligned.m8n8.x2.shared.b16 {%0,%1}, [%2];"
                 : "=r"(r[0]), "=r"(r[1]) : "r"(addr));
}
__device__ __forceinline__ void mma16816h(float* c, const uint32_t* a,
                                          uint32_t b0, uint32_t b1) {
    asm volatile(
        "mma.sync.aligned.m16n8k16.row.col.f32.f16.f16.f32 "
        "{%0,%1,%2,%3}, {%4,%5,%6,%7}, {%8,%9}, {%0,%1,%2,%3};"
        : "+f"(c[0]), "+f"(c[1]), "+f"(c[2]), "+f"(c[3])
        : "r"(a[0]), "r"(a[1]), "r"(a[2]), "r"(a[3]), "r"(b0), "r"(b1));
}

// ---------------------------------------------------------------------------
// B prep: g_B[co][k*288+q*72+j] from weights/W_lrf/b_lrf.
// ---------------------------------------------------------------------------
__global__ __launch_bounds__(128) void bprep_kernel(
    const float* __restrict__ W,       // [15][256][256]
    const float* __restrict__ W_lrf,   // [36][32]
    const float* __restrict__ b_lrf)   // [32]
{
    extern __shared__ float s[];       // [64][256]
    __shared__ float Wl[36 * 32];
    __shared__ float bl[32];

    const int k   = blockIdx.x;
    const int q   = blockIdx.y;
    const int co  = blockIdx.z * 128 + threadIdx.x;
    const int tid = threadIdx.x;

    for (int i = tid; i < 36 * 32; i += 128) Wl[i] = W_lrf[i];
    if (tid < 32) bl[tid] = b_lrf[tid];

    const float* Wb = W + ((size_t)k * 256 + q * 64) * 256;
    for (int i = tid; i < 64 * 256 / 4; i += 128) {
        reinterpret_cast<float4*>(s)[i] =
            reinterpret_cast<const float4*>(Wb)[i];
    }
    __syncthreads();

    float acc[37];
    #pragma unroll
    for (int t = 0; t < 37; t++) acc[t] = 0.0f;

    #pragma unroll 4
    for (int c = 0; c < 32; c++) {
        const float sv = s[(32 + c) * 256 + co];
        #pragma unroll
        for (int t = 0; t < 36; t++) acc[t] += Wl[t * 32 + c] * sv;
        acc[36] += bl[c] * sv;
    }

    __half h[72];
    #pragma unroll
    for (int j = 0; j < 32; j++) h[j] = __float2half_rn(s[j * 256 + co]);
    #pragma unroll
    for (int t = 0; t < 37; t++) h[32 + t] = __float2half_rn(acc[t]);
    h[69] = __float2half_rn(0.f); h[70] = h[69]; h[71] = h[69];

    __half* dst = &g_B[(size_t)co * BIGK2 + k * KROW + q * QW];
    #pragma unroll
    for (int v = 0; v < 9; v++)
        reinterpret_cast<uint4*>(dst)[v] = reinterpret_cast<const uint4*>(h)[v];
}

// ---------------------------------------------------------------------------
// Stage 1: geometry + fp16 MMA neighbor reduction. 128 threads/block.
//   w_sm [q][16 kp][32 m] fp16 (pads zero)
//   f_smT [288 j][32 m] fp16 (m pads zero)   j = q*72 + channel
//   per warp (q=wid): out[kp,j] = w @ f  via m16n8k16, staged in out_sm.
// ---------------------------------------------------------------------------
__global__ __launch_bounds__(128) void stage1_kernel(
    const float* __restrict__ q_pts,
    const float* __restrict__ s_pts,
    const int*   __restrict__ neighb_inds,
    const float* __restrict__ x,
    const float* __restrict__ q_lrf,
    const float* __restrict__ s_lrf,
    const float* __restrict__ kpts)
{
    __shared__ __align__(16) float ql[36];
    __shared__ __align__(16) float kp_s[48];
    __shared__ __align__(16) __half w_sm[4 * 16 * 32];   // 4096 B
    __shared__ __align__(16) __half f_smT[KROW * 32];    // 18432 B
    __shared__ __align__(16) __half out_sm[16 * KROW];   // 9216 B
    __shared__ int   ind_s[30];
    __shared__ float qp[3];

    const int n    = blockIdx.x;
    const int tid  = threadIdx.x;
    const int wid  = tid >> 5;
    const int lane = tid & 31;

    if (tid < 36) ql[tid]    = q_lrf[(size_t)n * 36 + tid];
    if (tid < 45) kp_s[tid]  = kpts[tid];
    if (tid < 3)  qp[tid]    = q_pts[(size_t)n * 3 + tid];
    if (tid < 30) ind_s[tid] = neighb_inds[(size_t)n * NEI + tid];

    // zero w_sm (covers kp=15 row and m=30,31 pads)
    #pragma unroll
    for (int i = tid; i < 2048 / 8; i += 128)
        reinterpret_cast<uint4*>(w_sm)[i] = make_uint4(0, 0, 0, 0);
    // zero m=30,31 columns of f_smT (one uint per row)
    #pragma unroll
    for (int j = tid; j < KROW; j += 128)
        *reinterpret_cast<uint32_t*>(&f_smT[j * 32 + 30]) = 0u;
    __syncthreads();

    // ---- x gather: f_smT[(q*72+c)][m] = x[ind][q*32+c] ----
    #pragma unroll 1
    for (int i = tid; i < NEI * CIN_; i += 128) {
        const int m  = i >> 7;
        const int qc = i & 127;
        const int ind = ind_s[m];
        float v = 0.0f;
        if (ind < S_SUP) v = x[(size_t)ind * CIN_ + qc];
        f_smT[((qc >> 5) * QW + (qc & 31)) * 32 + m] = __float2half_rn(v);
    }

    // ---- per-(m,q) geometry ----
    if (tid < 120) {
        const int m = tid >> 2;
        const int q = tid & 3;
        const int ind = ind_s[m];
        const bool valid = (ind < S_SUP);
        const int indc = valid ? ind : 0;
        const float* qlr = &ql[q * 9];

        const float nb0 = s_pts[(size_t)indc * 3 + 0] - qp[0];
        const float nb1 = s_pts[(size_t)indc * 3 + 1] - qp[1];
        const float nb2 = s_pts[(size_t)indc * 3 + 2] - qp[2];
        const float a0 = nb0 * qlr[0] + nb1 * qlr[3] + nb2 * qlr[6];
        const float a1 = nb0 * qlr[1] + nb1 * qlr[4] + nb2 * qlr[7];
        const float a2 = nb0 * qlr[2] + nb1 * qlr[5] + nb2 * qlr[8];

        #pragma unroll
        for (int k = 0; k < KP; k++) {
            const float d0 = a0 - kp_s[k * 3 + 0];
            const float d1 = a1 - kp_s[k * 3 + 1];
            const float d2 = a2 - kp_s[k * 3 + 2];
            float w = 1.0f - sqrtf(d0 * d0 + d1 * d1 + d2 * d2) * INV_EXT;
            w = fmaxf(w, 0.0f);
            w_sm[q * 512 + k * 32 + m] = __float2half_rn(valid ? w : 0.0f);
        }

        float sl[36];
        {
            const float4* p = reinterpret_cast<const float4*>(s_lrf + (size_t)indc * 36);
            #pragma unroll
            for (int t = 0; t < 9; t++) {
                const float4 v = p[t];
                sl[t * 4 + 0] = v.x; sl[t * 4 + 1] = v.y;
                sl[t * 4 + 2] = v.z; sl[t * 4 + 3] = v.w;
            }
        }
        const int jb = q * QW;
        #pragma unroll
        for (int s = 0; s < 4; s++)
            #pragma unroll
            for (int i = 0; i < 3; i++)
                #pragma unroll
                for (int j = 0; j < 3; j++) {
                    const float alv =
                        qlr[0 * 3 + i] * sl[s * 9 + 0 * 3 + j] +
                        qlr[1 * 3 + i] * sl[s * 9 + 1 * 3 + j] +
                        qlr[2 * 3 + i] * sl[s * 9 + 2 * 3 + j];
                    f_smT[(jb + 32 + s * 9 + i * 3 + j) * 32 + m] = __float2half_rn(alv);
                }
        f_smT[(jb + 68) * 32 + m] = __float2half_rn(valid ? 1.0f : 0.0f);
        f_smT[(jb + 69) * 32 + m] = __float2half_rn(0.0f);
        f_smT[(jb + 70) * 32 + m] = __float2half_rn(0.0f);
        f_smT[(jb + 71) * 32 + m] = __float2half_rn(0.0f);
    }
    __syncthreads();

    // ---- phase 2 (tensor cores): per warp q = wid ----
    {
        const int q = wid;
        const uint32_t fb = smem_u32(f_smT);
        const uint32_t wb = smem_u32(w_sm) + q * 512 * 2;

        float c[9][4];
        #pragma unroll
        for (int t = 0; t < 9; t++)
            #pragma unroll
            for (int e = 0; e < 4; e++) c[t][e] = 0.0f;

        // proven lane patterns (same as gemm_mma_kernel)
        const int a_row = lane & 15;
        const int a_kof = (lane >> 4) * 8;
        const int b_nof = ((lane >> 4) * 8) + (lane & 7);
        const int b_kof = ((lane >> 3) & 1) * 8;

        #pragma unroll
        for (int ks = 0; ks < 2; ks++) {
            const int k16 = ks * 16;
            uint32_t a[4];
            ldmx4(wb + (a_row * 32 + k16 + a_kof) * 2, a);

            uint32_t b[9][2];
            #pragma unroll
            for (int t = 0; t < 4; t++) {
                uint32_t r[4];
                ldmx4(fb + ((q * QW + t * 16 + b_nof) * 32 + k16 + b_kof) * 2, r);
                b[t * 2 + 0][0] = r[0]; b[t * 2 + 0][1] = r[1];
                b[t * 2 + 1][0] = r[2]; b[t * 2 + 1][1] = r[3];
            }
            {   // last n8 tile (j 64..71), x2: lanes 0-15 rows n, col k0/k8
                uint32_t r[2];
                ldmx2(fb + ((q * QW + 64 + (lane & 7)) * 32 + k16 +
                            ((lane >> 3) & 1) * 8) * 2, r);
                b[8][0] = r[0]; b[8][1] = r[1];
            }

            #pragma unroll
            for (int t = 0; t < 9; t++)
                mma16816h(c[t], a, b[t][0], b[t][1]);
        }

        // stage to out_sm [kp][288]; mask kp row 15
        const int r1 = lane >> 2;
        const int cb = q * QW + (lane & 3) * 2;
        #pragma unroll
        for (int t = 0; t < 9; t++) {
            const __half2 lo = __floats2half2_rn(c[t][0], c[t][1]);
            *reinterpret_cast<__half2*>(&out_sm[r1 * KROW + cb + t * 8]) = lo;
            if (r1 < 7) {
                const __half2 hi = __floats2half2_rn(c[t][2], c[t][3]);
                *reinterpret_cast<__half2*>(&out_sm[(r1 + 8) * KROW + cb + t * 8]) = hi;
            }
        }
    }
    __syncthreads();

    // ---- copy 15*288 = 4320 halfs to g_A (coalesced 16B) ----
    const uint4* src = reinterpret_cast<const uint4*>(out_sm);
    uint4* dst = reinterpret_cast<uint4*>(g_A + (size_t)n * BIGK2);
    #pragma unroll 2
    for (int i = tid; i < BIGK2 / 8; i += 128) dst[i] = src[i];
}

// ---------------------------------------------------------------------------
// Stage 2: fp16 mma.sync GEMM. CTA 128x128, BK=32, 4 warps (64x64 tiles).
// ---------------------------------------------------------------------------
__global__ __launch_bounds__(128)
void gemm_mma_kernel(const float* __restrict__ bias, float* __restrict__ C)
{
    extern __shared__ __align__(16) char sm[];
    const uint32_t s0 = smem_u32(sm);

    const int tid  = threadIdx.x;
    const int wid  = tid >> 5;
    const int lane = tid & 31;
    const int r0   = blockIdx.x * BM;
    const int c0   = blockIdx.y * BN;

    const int wm = (wid & 1) * 64;
    const int wn = (wid >> 1) * 64;

    float acc[4][8][4];
    #pragma unroll
    for (int i = 0; i < 4; i++)
        #pragma unroll
        for (int j = 0; j < 8; j++)
            #pragma unroll
            for (int e = 0; e < 4; e++) acc[i][j][e] = 0.0f;

    auto load_chunk = [&](int c, int buf) {
        const int kc = c * BK;
        const uint32_t base = s0 + buf * BUF_BYTES;
        #pragma unroll
        for (int it = 0; it < 4; it++) {
            const int i   = tid + it * 128;
            const int row = i >> 2;
            const int kq  = (i & 3) * 8;
            const uint32_t so = row * (LDS_ * 2) + kq * 2;
            cp16(base + so, &g_A[(size_t)(r0 + row) * BIGK2 + kc + kq]);
            cp16(base + MAT_BYTES + so, &g_B[(size_t)(c0 + row) * BIGK2 + kc + kq]);
        }
        cp_commit();
    };

    const int a_row = lane & 15;
    const int a_kof = (lane >> 4) * 8;
    const int b_nof = ((lane >> 4) * 8) + (lane & 7);
    const int b_kof = ((lane >> 3) & 1) * 8;

    load_chunk(0, 0);

    for (int c = 0; c < NKC; c++) {
        const int buf = c & 1;
        if (c + 1 < NKC) { load_chunk(c + 1, buf ^ 1); cp_wait1(); }
        else             { cp_wait0(); }
        __syncthreads();

        const uint32_t bA = s0 + buf * BUF_BYTES;
        const uint32_t bB = bA + MAT_BYTES;

        #pragma unroll
        for (int ks = 0; ks < 2; ks++) {
            const int k16 = ks * 16;
            uint32_t aH[4][4], bH[8][2];

            #pragma unroll
            for (int mt = 0; mt < 4; mt++) {
                const uint32_t off =
                    (wm + mt * 16 + a_row) * (LDS_ * 2) + (k16 + a_kof) * 2;
                ldmx4(bA + off, aH[mt]);
            }
            #pragma unroll
            for (int np = 0; np < 4; np++) {
                const uint32_t off =
                    (wn + np * 16 + b_nof) * (LDS_ * 2) + (k16 + b_kof) * 2;
                uint32_t t[4];
                ldmx4(bB + off, t);
                bH[np * 2 + 0][0] = t[0]; bH[np * 2 + 0][1] = t[1];
                bH[np * 2 + 1][0] = t[2]; bH[np * 2 + 1][1] = t[3];
            }

            #pragma unroll
            for (int mt = 0; mt < 4; mt++)
                #pragma unroll
                for (int nt = 0; nt < 8; nt++)
                    mma16816h(acc[mt][nt], aH[mt], bH[nt][0], bH[nt][1]);
        }
        __syncthreads();
    }

    const int erow = lane >> 2;
    const int ecol = (lane & 3) * 2;
    #pragma unroll
    for (int nt = 0; nt < 8; nt++) {
        const int col = c0 + wn + nt * 8 + ecol;
        const float b0 = bias[col], b1 = bias[col + 1];
        #pragma unroll
        for (int mt = 0; mt < 4; mt++) {
            #pragma unroll
            for (int h = 0; h < 2; h++) {
                const int row = r0 + wm + mt * 16 + erow + h * 8;
                if (row < N_Q) {
                    float v0 = acc[mt][nt][h * 2 + 0] + b0;
                    float v1 = acc[mt][nt][h * 2 + 1] + b1;
                    v0 = (v0 >= 0.f) ? v0 : 0.1f * v0;
                    v1 = (v1 >= 0.f) ? v1 : 0.1f * v1;
                    *reinterpret_cast<float2*>(&C[(size_t)row * COUT_ + col]) =
                        make_float2(v0, v1);
                }
            }
        }
    }
}

// ---------------------------------------------------------------------------
// Launch
// ---------------------------------------------------------------------------
extern "C" void kernel_launch(void* const* d_in, const int* in_sizes, int n_in,
                              void* d_out, int out_size) {
    const float* q_pts   = (const float*)d_in[0];
    const float* s_pts   = (const float*)d_in[1];
    const int*   inds    = (const int*)  d_in[2];
    const float* x       = (const float*)d_in[3];
    const float* q_lrf   = (const float*)d_in[4];
    const float* s_lrf   = (const float*)d_in[5];
    const float* kpts    = (const float*)d_in[6];
    const float* weights = (const float*)d_in[7];
    const float* W_lrf   = (const float*)d_in[8];
    const float* b_lrf   = (const float*)d_in[9];
    const float* bias    = (const float*)d_in[10];
    float* out = (float*)d_out;

    cudaFuncSetAttribute(bprep_kernel,
                         cudaFuncAttributeMaxDynamicSharedMemorySize, 65536);
    cudaFuncSetAttribute(gemm_mma_kernel,
                         cudaFuncAttributeMaxDynamicSharedMemorySize, SMEM_DYN);

    bprep_kernel<<<dim3(KP, 4, 2), 128, 65536>>>(weights, W_lrf, b_lrf);

    stage1_kernel<<<N_Q, 128>>>(q_pts, s_pts, inds, x, q_lrf, s_lrf, kpts);

    dim3 ggrid(M_PAD / BM, COUT_ / BN);
    gemm_mma_kernel<<<ggrid, 128, SMEM_DYN>>>(bias, out);
}

// round 8
// speedup vs baseline: 1.2159x; 1.2159x over previous
#include <cuda_runtime.h>
#include <cuda_fp16.h>
#include <cstdint>
#include <math.h>

// ---------------------------------------------------------------------------
// Problem constants
// ---------------------------------------------------------------------------
namespace {
constexpr int N_Q   = 20000;
constexpr int S_SUP = 20000;
constexpr int NEI   = 30;
constexpr int KP    = 15;
constexpr int CIN_  = 128;
constexpr int COUT_ = 256;
constexpr float INV_EXT = 20.0f;

constexpr int M_PAD = 20096;        // 157*128

// Extended-K layout: per k: 4 q-groups of 72 slots
//   j<32: x part; j in [32,68): 36 al channels; j=68: validity; j>68: pad
constexpr int QW    = 72;
constexpr int KROW  = 4 * QW;             // 288
constexpr int BIGK2 = KP * KROW;          // 4320

// GEMM tiling
constexpr int BM = 128, BN = 128, BK = 32;
constexpr int NKC = BIGK2 / BK;           // 135
constexpr int LDS_ = 40;                  // smem row stride (fp16 elems)
constexpr int MAT_BYTES = 128 * LDS_ * 2; // 10240
constexpr int BUF_BYTES = 2 * MAT_BYTES;  // A|B = 20480
constexpr int SMEM_DYN  = 2 * BUF_BYTES;  // 40960 double-buffered
}

// ---------------------------------------------------------------------------
// Scratch (device globals, zero-initialized; pad rows never written)
// ---------------------------------------------------------------------------
__device__ __half g_A[(size_t)M_PAD * BIGK2];
__device__ __half g_B[(size_t)COUT_ * BIGK2];   // [co][kidx]

// ---------------------------------------------------------------------------
// PTX helpers (sm_80+ baseline; legal on family target)
// ---------------------------------------------------------------------------
__device__ __forceinline__ uint32_t smem_u32(const void* p) {
    uint32_t a;
    asm("{ .reg .u64 t; cvta.to.shared.u64 t, %1; cvt.u32.u64 %0, t; }"
        : "=r"(a) : "l"(p));
    return a;
}
__device__ __forceinline__ void cp16(uint32_t s, const void* g) {
    asm volatile("cp.async.cg.shared.global [%0], [%1], 16;" :: "r"(s), "l"(g));
}
// zero-fill variants: src_size = 0 -> no global read, smem zero-filled
__device__ __forceinline__ void cp16z(uint32_t s, const void* g, bool v) {
    const int sz = v ? 16 : 0;
    asm volatile("cp.async.cg.shared.global [%0], [%1], 16, %2;"
                 :: "r"(s), "l"(g), "r"(sz));
}
__device__ __forceinline__ void cp4z(uint32_t s, const void* g, bool v) {
    const int sz = v ? 4 : 0;
    asm volatile("cp.async.ca.shared.global [%0], [%1], 4, %2;"
                 :: "r"(s), "l"(g), "r"(sz));
}
__device__ __forceinline__ void cp_commit() {
    asm volatile("cp.async.commit_group;");
}
__device__ __forceinline__ void cp_wait1() {
    asm volatile("cp.async.wait_group 1;" ::: "memory");
}
__device__ __forceinline__ void cp_wait0() {
    asm volatile("cp.async.wait_group 0;" ::: "memory");
}
__device__ __forceinline__ void ldmx4(uint32_t addr, uint32_t* r) {
    asm volatile("ldmatrix.sync.aligned.m8n8.x4.shared.b16 {%0,%1,%2,%3}, [%4];"
                 : "=r"(r[0]), "=r"(r[1]), "=r"(r[2]), "=r"(r[3]) : "r"(addr));
}
__device__ __forceinline__ void mma16816h(float* c, const uint32_t* a,
                                          uint32_t b0, uint32_t b1) {
    asm volatile(
        "mma.sync.aligned.m16n8k16.row.col.f32.f16.f16.f32 "
        "{%0,%1,%2,%3}, {%4,%5,%6,%7}, {%8,%9}, {%0,%1,%2,%3};"
        : "+f"(c[0]), "+f"(c[1]), "+f"(c[2]), "+f"(c[3])
        : "r"(a[0]), "r"(a[1]), "r"(a[2]), "r"(a[3]), "r"(b0), "r"(b1));
}

// ---------------------------------------------------------------------------
// B prep: g_B[co][k*288+q*72+j] from weights/W_lrf/b_lrf.
// ---------------------------------------------------------------------------
__global__ __launch_bounds__(128) void bprep_kernel(
    const float* __restrict__ W,       // [15][256][256]
    const float* __restrict__ W_lrf,   // [36][32]
    const float* __restrict__ b_lrf)   // [32]
{
    extern __shared__ float s[];       // [64][256]
    __shared__ float Wl[36 * 32];
    __shared__ float bl[32];

    const int k   = blockIdx.x;
    const int q   = blockIdx.y;
    const int co  = blockIdx.z * 128 + threadIdx.x;
    const int tid = threadIdx.x;

    for (int i = tid; i < 36 * 32; i += 128) Wl[i] = W_lrf[i];
    if (tid < 32) bl[tid] = b_lrf[tid];

    const float* Wb = W + ((size_t)k * 256 + q * 64) * 256;
    for (int i = tid; i < 64 * 256 / 4; i += 128) {
        reinterpret_cast<float4*>(s)[i] =
            reinterpret_cast<const float4*>(Wb)[i];
    }
    __syncthreads();

    float acc[37];
    #pragma unroll
    for (int t = 0; t < 37; t++) acc[t] = 0.0f;

    #pragma unroll 4
    for (int c = 0; c < 32; c++) {
        const float sv = s[(32 + c) * 256 + co];
        #pragma unroll
        for (int t = 0; t < 36; t++) acc[t] += Wl[t * 32 + c] * sv;
        acc[36] += bl[c] * sv;
    }

    __half h[72];
    #pragma unroll
    for (int j = 0; j < 32; j++) h[j] = __float2half_rn(s[j * 256 + co]);
    #pragma unroll
    for (int t = 0; t < 37; t++) h[32 + t] = __float2half_rn(acc[t]);
    h[69] = __float2half_rn(0.f); h[70] = h[69]; h[71] = h[69];

    __half* dst = &g_B[(size_t)co * BIGK2 + k * KROW + q * QW];
    #pragma unroll
    for (int v = 0; v < 9; v++)
        reinterpret_cast<uint4*>(dst)[v] = reinterpret_cast<const uint4*>(h)[v];
}

// ---------------------------------------------------------------------------
// Stage 1: cp.async-staged gather + geometry + FFMA neighbor reduction.
// 160 threads/block, one block per query.
// ---------------------------------------------------------------------------
__global__ __launch_bounds__(160) void stage1_kernel(
    const float* __restrict__ q_pts,
    const float* __restrict__ s_pts,
    const int*   __restrict__ neighb_inds,
    const float* __restrict__ x,
    const float* __restrict__ q_lrf,
    const float* __restrict__ s_lrf,
    const float* __restrict__ kpts)
{
    __shared__ __align__(16) float ql[36];
    __shared__ __align__(16) float kp_s[48];
    __shared__ __align__(16) float w_sm[16 * 120];     // [k][m*4+q], k=15 pad
    __shared__ __align__(16) float f_sm[30 * KROW];    // [m][q*72 + j]
    __shared__ __align__(16) float slrf_sm[30 * 36];   // [m][36]
    __shared__ __align__(16) float spts_sm[30 * 4];    // [m][xyz-]
    __shared__ int   ind_s[30];
    __shared__ float qp[3];

    const int n   = blockIdx.x;
    const int tid = threadIdx.x;

    if (tid < 36) ql[tid]    = q_lrf[(size_t)n * 36 + tid];
    if (tid < 45) kp_s[tid]  = kpts[tid];
    if (tid < 3)  qp[tid]    = q_pts[(size_t)n * 3 + tid];
    if (tid < 30) ind_s[tid] = neighb_inds[(size_t)n * NEI + tid];
    if (tid < 120) w_sm[15 * 120 + tid] = 0.0f;
    __syncthreads();   // ind_s ready for cp.async issue

    const uint32_t fb    = smem_u32(f_sm);
    const uint32_t slb   = smem_u32(slrf_sm);
    const uint32_t spb   = smem_u32(spts_sm);

    // ---- async gather: x rows into j<32 slots (960 x 16B) ----
    #pragma unroll
    for (int it = 0; it < 6; it++) {
        const int i = tid + it * 160;
        if (i < 960) {
            const int m   = i >> 5;        // /32
            const int q   = (i >> 3) & 3;
            const int c4  = i & 7;
            const int ind = ind_s[m];
            const bool v  = (ind < S_SUP);
            cp16z(fb + (m * KROW + q * QW + c4 * 4) * 4,
                  x + (size_t)(v ? ind : 0) * CIN_ + q * 32 + c4 * 4, v);
        }
    }
    // ---- async gather: s_lrf rows (270 x 16B) ----
    #pragma unroll
    for (int it = 0; it < 2; it++) {
        const int i = tid + it * 160;
        if (i < 270) {
            const int m = i / 9, t = i % 9;
            const int ind = ind_s[m];
            const bool v  = (ind < S_SUP);
            cp16z(slb + (m * 36 + t * 4) * 4,
                  s_lrf + (size_t)(v ? ind : 0) * 36 + t * 4, v);
        }
    }
    // ---- async gather: s_pts (3 x 4B per m; 12B row stride is only
    //      4B-aligned, so all copies must be 4B) ----
    if (tid < 90) {
        const int m = tid / 3, e = tid % 3;
        const int ind = ind_s[m];
        const bool v  = (ind < S_SUP);
        cp4z(spb + (m * 4 + e) * 4, s_pts + (size_t)(v ? ind : 0) * 3 + e, v);
    }
    cp_commit();
    cp_wait0();
    __syncthreads();

    // ---- per-(m,q) geometry (reads staged smem only) ----
    if (tid < 120) {
        const int m = tid >> 2;
        const int q = tid & 3;
        const int ind = ind_s[m];
        const bool valid = (ind < S_SUP);
        const float* qlr = &ql[q * 9];

        const float nb0 = spts_sm[m * 4 + 0] - qp[0];
        const float nb1 = spts_sm[m * 4 + 1] - qp[1];
        const float nb2 = spts_sm[m * 4 + 2] - qp[2];
        const float a0 = nb0 * qlr[0] + nb1 * qlr[3] + nb2 * qlr[6];
        const float a1 = nb0 * qlr[1] + nb1 * qlr[4] + nb2 * qlr[7];
        const float a2 = nb0 * qlr[2] + nb1 * qlr[5] + nb2 * qlr[8];

        #pragma unroll
        for (int k = 0; k < KP; k++) {
            const float d0 = a0 - kp_s[k * 3 + 0];
            const float d1 = a1 - kp_s[k * 3 + 1];
            const float d2 = a2 - kp_s[k * 3 + 2];
            float w = 1.0f - sqrtf(d0 * d0 + d1 * d1 + d2 * d2) * INV_EXT;
            w = fmaxf(w, 0.0f);
            w_sm[k * 120 + m * 4 + q] = valid ? w : 0.0f;
        }

        float sl[36];
        {
            const float4* p = reinterpret_cast<const float4*>(&slrf_sm[m * 36]);
            #pragma unroll
            for (int t = 0; t < 9; t++) {
                const float4 v = p[t];
                sl[t * 4 + 0] = v.x; sl[t * 4 + 1] = v.y;
                sl[t * 4 + 2] = v.z; sl[t * 4 + 3] = v.w;
            }
        }
        float* fr = &f_sm[m * KROW + q * QW];
        #pragma unroll
        for (int s = 0; s < 4; s++)
            #pragma unroll
            for (int i = 0; i < 3; i++)
                #pragma unroll
                for (int j = 0; j < 3; j++) {
                    fr[32 + s * 9 + i * 3 + j] =
                        qlr[0 * 3 + i] * sl[s * 9 + 0 * 3 + j] +
                        qlr[1 * 3 + i] * sl[s * 9 + 1 * 3 + j] +
                        qlr[2 * 3 + i] * sl[s * 9 + 2 * 3 + j];
                }
        fr[68] = valid ? 1.0f : 0.0f;
        fr[69] = 0.0f; fr[70] = 0.0f; fr[71] = 0.0f;
    }
    __syncthreads();

    // ---- phase 2: A[q,k,j] = sum_m w[q,k,m] * f[m,q,j] ----
    // 144 tasks on 160 threads: (h,q,c17), 8 k x float4 each.
    if (tid < 144) {
        const int c17 = tid % 18;
        const int rem = tid / 18;
        const int q2  = rem & 3;
        const int h   = rem >> 2;
        const int k0  = h * 8;

        float4 acc[8];
        #pragma unroll
        for (int i = 0; i < 8; i++) acc[i] = make_float4(0.f, 0.f, 0.f, 0.f);

        #pragma unroll 1
        for (int m = 0; m < NEI; m++) {
            const float4 f4 = *reinterpret_cast<const float4*>(
                &f_sm[m * KROW + q2 * QW + c17 * 4]);
            const float* wp = &w_sm[k0 * 120 + m * 4 + q2];
            #pragma unroll
            for (int kl = 0; kl < 8; kl++) {
                const float wv = wp[kl * 120];
                acc[kl].x += wv * f4.x; acc[kl].y += wv * f4.y;
                acc[kl].z += wv * f4.z; acc[kl].w += wv * f4.w;
            }
        }

        #pragma unroll
        for (int kl = 0; kl < 8; kl++) {
            const int k = k0 + kl;
            if (k < KP) {
                const size_t off = (size_t)n * BIGK2 + k * KROW + q2 * QW + c17 * 4;
                __half2 p0 = __floats2half2_rn(acc[kl].x, acc[kl].y);
                __half2 p1 = __floats2half2_rn(acc[kl].z, acc[kl].w);
                uint2 pk;
                pk.x = *reinterpret_cast<uint32_t*>(&p0);
                pk.y = *reinterpret_cast<uint32_t*>(&p1);
                *reinterpret_cast<uint2*>(&g_A[off]) = pk;
            }
        }
    }
}

// ---------------------------------------------------------------------------
// Stage 2: fp16 mma.sync GEMM. CTA 128x128, BK=32, 4 warps (64x64 tiles).
// ---------------------------------------------------------------------------
__global__ __launch_bounds__(128)
void gemm_mma_kernel(const float* __restrict__ bias, float* __restrict__ C)
{
    extern __shared__ __align__(16) char sm[];
    const uint32_t s0 = smem_u32(sm);

    const int tid  = threadIdx.x;
    const int wid  = tid >> 5;
    const int lane = tid & 31;
    const int r0   = blockIdx.x * BM;
    const int c0   = blockIdx.y * BN;

    const int wm = (wid & 1) * 64;
    const int wn = (wid >> 1) * 64;

    float acc[4][8][4];
    #pragma unroll
    for (int i = 0; i < 4; i++)
        #pragma unroll
        for (int j = 0; j < 8; j++)
            #pragma unroll
            for (int e = 0; e < 4; e++) acc[i][j][e] = 0.0f;

    auto load_chunk = [&](int c, int buf) {
        const int kc = c * BK;
        const uint32_t base = s0 + buf * BUF_BYTES;
        #pragma unroll
        for (int it = 0; it < 4; it++) {
            const int i   = tid + it * 128;
            const int row = i >> 2;
            const int kq  = (i & 3) * 8;
            const uint32_t so = row * (LDS_ * 2) + kq * 2;
            cp16(base + so, &g_A[(size_t)(r0 + row) * BIGK2 + kc + kq]);
            cp16(base + MAT_BYTES + so, &g_B[(size_t)(c0 + row) * BIGK2 + kc + kq]);
        }
        cp_commit();
    };

    const int a_row = lane & 15;
    const int a_kof = (lane >> 4) * 8;
    const int b_nof = ((lane >> 4) * 8) + (lane & 7);
    const int b_kof = ((lane >> 3) & 1) * 8;

    load_chunk(0, 0);

    for (int c = 0; c < NKC; c++) {
        const int buf = c & 1;
        if (c + 1 < NKC) { load_chunk(c + 1, buf ^ 1); cp_wait1(); }
        else             { cp_wait0(); }
        __syncthreads();

        const uint32_t bA = s0 + buf * BUF_BYTES;
        const uint32_t bB = bA + MAT_BYTES;

        #pragma unroll
        for (int ks = 0; ks < 2; ks++) {
            const int k16 = ks * 16;
            uint32_t aH[4][4], bH[8][2];

            #pragma unroll
            for (int mt = 0; mt < 4; mt++) {
                const uint32_t off =
                    (wm + mt * 16 + a_row) * (LDS_ * 2) + (k16 + a_kof) * 2;
                ldmx4(bA + off, aH[mt]);
            }
            #pragma unroll
            for (int np = 0; np < 4; np++) {
                const uint32_t off =
                    (wn + np * 16 + b_nof) * (LDS_ * 2) + (k16 + b_kof) * 2;
                uint32_t t[4];
                ldmx4(bB + off, t);
                bH[np * 2 + 0][0] = t[0]; bH[np * 2 + 0][1] = t[1];
                bH[np * 2 + 1][0] = t[2]; bH[np * 2 + 1][1] = t[3];
            }

            #pragma unroll
            for (int mt = 0; mt < 4; mt++)
                #pragma unroll
                for (int nt = 0; nt < 8; nt++)
                    mma16816h(acc[mt][nt], aH[mt], bH[nt][0], bH[nt][1]);
        }
        __syncthreads();
    }

    const int erow = lane >> 2;
    const int ecol = (lane & 3) * 2;
    #pragma unroll
    for (int nt = 0; nt < 8; nt++) {
        const int col = c0 + wn + nt * 8 + ecol;
        const float b0 = bias[col], b1 = bias[col + 1];
        #pragma unroll
        for (int mt = 0; mt < 4; mt++) {
            #pragma unroll
            for (int h = 0; h < 2; h++) {
                const int row = r0 + wm + mt * 16 + erow + h * 8;
                if (row < N_Q) {
                    float v0 = acc[mt][nt][h * 2 + 0] + b0;
                    float v1 = acc[mt][nt][h * 2 + 1] + b1;
                    v0 = (v0 >= 0.f) ? v0 : 0.1f * v0;
                    v1 = (v1 >= 0.f) ? v1 : 0.1f * v1;
                    *reinterpret_cast<float2*>(&C[(size_t)row * COUT_ + col]) =
                        make_float2(v0, v1);
                }
            }
        }
    }
}

// ---------------------------------------------------------------------------
// Launch
// ---------------------------------------------------------------------------
extern "C" void kernel_launch(void* const* d_in, const int* in_sizes, int n_in,
                              void* d_out, int out_size) {
    const float* q_pts   = (const float*)d_in[0];
    const float* s_pts   = (const float*)d_in[1];
    const int*   inds    = (const int*)  d_in[2];
    const float* x       = (const float*)d_in[3];
    const float* q_lrf   = (const float*)d_in[4];
    const float* s_lrf   = (const float*)d_in[5];
    const float* kpts    = (const float*)d_in[6];
    const float* weights = (const float*)d_in[7];
    const float* W_lrf   = (const float*)d_in[8];
    const float* b_lrf   = (const float*)d_in[9];
    const float* bias    = (const float*)d_in[10];
    float* out = (float*)d_out;

    cudaFuncSetAttribute(bprep_kernel,
                         cudaFuncAttributeMaxDynamicSharedMemorySize, 65536);
    cudaFuncSetAttribute(gemm_mma_kernel,
                         cudaFuncAttributeMaxDynamicSharedMemorySize, SMEM_DYN);

    bprep_kernel<<<dim3(KP, 4, 2), 128, 65536>>>(weights, W_lrf, b_lrf);

    stage1_kernel<<<N_Q, 160>>>(q_pts, s_pts, inds, x, q_lrf, s_lrf, kpts);

    dim3 ggrid(M_PAD / BM, COUT_ / BN);
    gemm_mma_kernel<<<ggrid, 128, SMEM_DYN>>>(bias, out);
}

// round 9
// speedup vs baseline: 1.2811x; 1.0536x over previous
#include <cuda_runtime.h>
#include <cuda_fp16.h>
#include <cstdint>
#include <math.h>

// ---------------------------------------------------------------------------
// Problem constants
// ---------------------------------------------------------------------------
namespace {
constexpr int N_Q   = 20000;
constexpr int S_SUP = 20000;
constexpr int NEI   = 30;
constexpr int KP    = 15;
constexpr int CIN_  = 128;
constexpr int COUT_ = 256;
constexpr float INV_EXT = 20.0f;

constexpr int M_PAD = 20096;        // 157*128

// Extended-K layout: per k: 4 q-groups of 72 slots
//   j<32: x part; j in [32,68): 36 al channels; j=68: validity; j>68: pad
constexpr int QW    = 72;
constexpr int KROW  = 4 * QW;             // 288
constexpr int BIGK2 = KP * KROW;          // 4320

// GEMM tiling
constexpr int BM = 128, BN = 128, BK = 48;
constexpr int NKC = BIGK2 / BK;           // 90
constexpr int LDS_ = 56;                  // smem row stride (fp16 elems)
constexpr int MAT_BYTES = 128 * LDS_ * 2; // 14336
constexpr int BUF_BYTES = 2 * MAT_BYTES;  // A|B = 28672
constexpr int SMEM_DYN  = 2 * BUF_BYTES;  // 57344 double-buffered
}

// ---------------------------------------------------------------------------
// Scratch (device globals, zero-initialized; pad rows never written)
// ---------------------------------------------------------------------------
__device__ __half g_A[(size_t)M_PAD * BIGK2];
__device__ __half g_B[(size_t)COUT_ * BIGK2];   // [co][kidx]

// ---------------------------------------------------------------------------
// PTX helpers (sm_80+/sm_100-family baseline; legal on family target)
// ---------------------------------------------------------------------------
__device__ __forceinline__ uint32_t smem_u32(const void* p) {
    uint32_t a;
    asm("{ .reg .u64 t; cvta.to.shared.u64 t, %1; cvt.u32.u64 %0, t; }"
        : "=r"(a) : "l"(p));
    return a;
}
__device__ __forceinline__ void cp16(uint32_t s, const void* g) {
    asm volatile("cp.async.cg.shared.global [%0], [%1], 16;" :: "r"(s), "l"(g));
}
// zero-fill variants: src_size = 0 -> no global read, smem zero-filled
__device__ __forceinline__ void cp16z(uint32_t s, const void* g, bool v) {
    const int sz = v ? 16 : 0;
    asm volatile("cp.async.cg.shared.global [%0], [%1], 16, %2;"
                 :: "r"(s), "l"(g), "r"(sz));
}
__device__ __forceinline__ void cp4z(uint32_t s, const void* g, bool v) {
    const int sz = v ? 4 : 0;
    asm volatile("cp.async.ca.shared.global [%0], [%1], 4, %2;"
                 :: "r"(s), "l"(g), "r"(sz));
}
__device__ __forceinline__ void cp_commit() {
    asm volatile("cp.async.commit_group;");
}
__device__ __forceinline__ void cp_wait1() {
    asm volatile("cp.async.wait_group 1;" ::: "memory");
}
__device__ __forceinline__ void cp_wait0() {
    asm volatile("cp.async.wait_group 0;" ::: "memory");
}
__device__ __forceinline__ void ldmx4(uint32_t addr, uint32_t* r) {
    asm volatile("ldmatrix.sync.aligned.m8n8.x4.shared.b16 {%0,%1,%2,%3}, [%4];"
                 : "=r"(r[0]), "=r"(r[1]), "=r"(r[2]), "=r"(r[3]) : "r"(addr));
}
__device__ __forceinline__ void mma16816h(float* c, const uint32_t* a,
                                          uint32_t b0, uint32_t b1) {
    asm volatile(
        "mma.sync.aligned.m16n8k16.row.col.f32.f16.f16.f32 "
        "{%0,%1,%2,%3}, {%4,%5,%6,%7}, {%8,%9}, {%0,%1,%2,%3};"
        : "+f"(c[0]), "+f"(c[1]), "+f"(c[2]), "+f"(c[3])
        : "r"(a[0]), "r"(a[1]), "r"(a[2]), "r"(a[3]), "r"(b0), "r"(b1));
}
// packed fp32x2 (sm_100-family PTX; NOT an 'a'-suffix feature)
typedef unsigned long long u64t;
__device__ __forceinline__ u64t fma2(u64t a, u64t b, u64t c) {
    u64t d;
    asm("fma.rn.f32x2 %0, %1, %2, %3;" : "=l"(d) : "l"(a), "l"(b), "l"(c));
    return d;
}
__device__ __forceinline__ u64t pack2(float lo, float hi) {
    u64t d;
    asm("mov.b64 %0, {%1, %2};" : "=l"(d) : "f"(lo), "f"(hi));
    return d;
}
__device__ __forceinline__ void unpack2(u64t v, float& lo, float& hi) {
    asm("mov.b64 {%0, %1}, %2;" : "=f"(lo), "=f"(hi) : "l"(v));
}

// ---------------------------------------------------------------------------
// B prep: g_B[co][k*288+q*72+j] from weights/W_lrf/b_lrf.
// ---------------------------------------------------------------------------
__global__ __launch_bounds__(128) void bprep_kernel(
    const float* __restrict__ W,       // [15][256][256]
    const float* __restrict__ W_lrf,   // [36][32]
    const float* __restrict__ b_lrf)   // [32]
{
    extern __shared__ float s[];       // [64][256]
    __shared__ float Wl[36 * 32];
    __shared__ float bl[32];

    const int k   = blockIdx.x;
    const int q   = blockIdx.y;
    const int co  = blockIdx.z * 128 + threadIdx.x;
    const int tid = threadIdx.x;

    for (int i = tid; i < 36 * 32; i += 128) Wl[i] = W_lrf[i];
    if (tid < 32) bl[tid] = b_lrf[tid];

    const float* Wb = W + ((size_t)k * 256 + q * 64) * 256;
    for (int i = tid; i < 64 * 256 / 4; i += 128) {
        reinterpret_cast<float4*>(s)[i] =
            reinterpret_cast<const float4*>(Wb)[i];
    }
    __syncthreads();

    float acc[37];
    #pragma unroll
    for (int t = 0; t < 37; t++) acc[t] = 0.0f;

    #pragma unroll 4
    for (int c = 0; c < 32; c++) {
        const float sv = s[(32 + c) * 256 + co];
        #pragma unroll
        for (int t = 0; t < 36; t++) acc[t] += Wl[t * 32 + c] * sv;
        acc[36] += bl[c] * sv;
    }

    __half h[72];
    #pragma unroll
    for (int j = 0; j < 32; j++) h[j] = __float2half_rn(s[j * 256 + co]);
    #pragma unroll
    for (int t = 0; t < 37; t++) h[32 + t] = __float2half_rn(acc[t]);
    h[69] = __float2half_rn(0.f); h[70] = h[69]; h[71] = h[69];

    __half* dst = &g_B[(size_t)co * BIGK2 + k * KROW + q * QW];
    #pragma unroll
    for (int v = 0; v < 9; v++)
        reinterpret_cast<uint4*>(dst)[v] = reinterpret_cast<const uint4*>(h)[v];
}

// ---------------------------------------------------------------------------
// Stage 1: cp.async-staged gather + geometry + f32x2 neighbor reduction.
// 160 threads/block, one block per query.
// ---------------------------------------------------------------------------
__global__ __launch_bounds__(160) void stage1_kernel(
    const float* __restrict__ q_pts,
    const float* __restrict__ s_pts,
    const int*   __restrict__ neighb_inds,
    const float* __restrict__ x,
    const float* __restrict__ q_lrf,
    const float* __restrict__ s_lrf,
    const float* __restrict__ kpts)
{
    __shared__ __align__(16) float ql[36];
    __shared__ __align__(16) float kp_s[48];
    __shared__ __align__(16) float2 w2_sm[8 * 30 * 4];  // [k2][m][q] k-pairs
    __shared__ __align__(16) float f_sm[30 * KROW];     // [m][q*72 + j]
    __shared__ __align__(16) float slrf_sm[30 * 36];    // [m][36]
    __shared__ __align__(16) float spts_sm[30 * 4];     // [m][xyz-]
    __shared__ int   ind_s[30];
    __shared__ float qp[3];

    const int n   = blockIdx.x;
    const int tid = threadIdx.x;

    if (tid < 36) ql[tid]    = q_lrf[(size_t)n * 36 + tid];
    if (tid < 45) kp_s[tid]  = kpts[tid];
    if (tid < 3)  qp[tid]    = q_pts[(size_t)n * 3 + tid];
    if (tid < 30) ind_s[tid] = neighb_inds[(size_t)n * NEI + tid];
    __syncthreads();   // ind_s ready for cp.async issue

    const uint32_t fb    = smem_u32(f_sm);
    const uint32_t slb   = smem_u32(slrf_sm);
    const uint32_t spb   = smem_u32(spts_sm);

    // ---- async gather: x rows into j<32 slots (960 x 16B) ----
    #pragma unroll
    for (int it = 0; it < 6; it++) {
        const int i = tid + it * 160;
        if (i < 960) {
            const int m   = i >> 5;        // /32
            const int q   = (i >> 3) & 3;
            const int c4  = i & 7;
            const int ind = ind_s[m];
            const bool v  = (ind < S_SUP);
            cp16z(fb + (m * KROW + q * QW + c4 * 4) * 4,
                  x + (size_t)(v ? ind : 0) * CIN_ + q * 32 + c4 * 4, v);
        }
    }
    // ---- async gather: s_lrf rows (270 x 16B) ----
    #pragma unroll
    for (int it = 0; it < 2; it++) {
        const int i = tid + it * 160;
        if (i < 270) {
            const int m = i / 9, t = i % 9;
            const int ind = ind_s[m];
            const bool v  = (ind < S_SUP);
            cp16z(slb + (m * 36 + t * 4) * 4,
                  s_lrf + (size_t)(v ? ind : 0) * 36 + t * 4, v);
        }
    }
    // ---- async gather: s_pts (3 x 4B per m; 12B stride only 4B-aligned) ----
    if (tid < 90) {
        const int m = tid / 3, e = tid % 3;
        const int ind = ind_s[m];
        const bool v  = (ind < S_SUP);
        cp4z(spb + (m * 4 + e) * 4, s_pts + (size_t)(v ? ind : 0) * 3 + e, v);
    }
    cp_commit();
    cp_wait0();
    __syncthreads();

    // ---- per-(m,q) geometry (reads staged smem only) ----
    if (tid < 120) {
        const int m = tid >> 2;
        const int q = tid & 3;
        const int ind = ind_s[m];
        const bool valid = (ind < S_SUP);
        const float* qlr = &ql[q * 9];

        const float nb0 = spts_sm[m * 4 + 0] - qp[0];
        const float nb1 = spts_sm[m * 4 + 1] - qp[1];
        const float nb2 = spts_sm[m * 4 + 2] - qp[2];
        const float a0 = nb0 * qlr[0] + nb1 * qlr[3] + nb2 * qlr[6];
        const float a1 = nb0 * qlr[1] + nb1 * qlr[4] + nb2 * qlr[7];
        const float a2 = nb0 * qlr[2] + nb1 * qlr[5] + nb2 * qlr[8];

        float wv[16];
        #pragma unroll
        for (int k = 0; k < KP; k++) {
            const float d0 = a0 - kp_s[k * 3 + 0];
            const float d1 = a1 - kp_s[k * 3 + 1];
            const float d2 = a2 - kp_s[k * 3 + 2];
            float w = 1.0f - sqrtf(d0 * d0 + d1 * d1 + d2 * d2) * INV_EXT;
            w = fmaxf(w, 0.0f);
            wv[k] = valid ? w : 0.0f;
        }
        wv[15] = 0.0f;
        #pragma unroll
        for (int k2 = 0; k2 < 8; k2++)
            w2_sm[(k2 * 30 + m) * 4 + q] = make_float2(wv[2 * k2], wv[2 * k2 + 1]);

        float sl[36];
        {
            const float4* p = reinterpret_cast<const float4*>(&slrf_sm[m * 36]);
            #pragma unroll
            for (int t = 0; t < 9; t++) {
                const float4 v = p[t];
                sl[t * 4 + 0] = v.x; sl[t * 4 + 1] = v.y;
                sl[t * 4 + 2] = v.z; sl[t * 4 + 3] = v.w;
            }
        }
        float* fr = &f_sm[m * KROW + q * QW];
        #pragma unroll
        for (int s = 0; s < 4; s++)
            #pragma unroll
            for (int i = 0; i < 3; i++)
                #pragma unroll
                for (int j = 0; j < 3; j++) {
                    fr[32 + s * 9 + i * 3 + j] =
                        qlr[0 * 3 + i] * sl[s * 9 + 0 * 3 + j] +
                        qlr[1 * 3 + i] * sl[s * 9 + 1 * 3 + j] +
                        qlr[2 * 3 + i] * sl[s * 9 + 2 * 3 + j];
                }
        fr[68] = valid ? 1.0f : 0.0f;
        fr[69] = 0.0f; fr[70] = 0.0f; fr[71] = 0.0f;
    }
    __syncthreads();

    // ---- phase 2 (f32x2): A[q,2k2+e,j] = sum_m w[q,k,m] * f[m,q,j] ----
    // 144 tasks on 160 threads: (h,q,c17); 4 k-pairs x 4 channels each.
    if (tid < 144) {
        const int c17 = tid % 18;
        const int rem = tid / 18;
        const int q2  = rem & 3;
        const int h   = rem >> 2;          // k2 base = h*4

        u64t acc[4][4];
        #pragma unroll
        for (int i = 0; i < 4; i++)
            #pragma unroll
            for (int j = 0; j < 4; j++) acc[i][j] = 0ull;

        #pragma unroll 1
        for (int m = 0; m < NEI; m++) {
            const float4 f4 = *reinterpret_cast<const float4*>(
                &f_sm[m * KROW + q2 * QW + c17 * 4]);
            u64t fp[4];
            fp[0] = pack2(f4.x, f4.x);
            fp[1] = pack2(f4.y, f4.y);
            fp[2] = pack2(f4.z, f4.z);
            fp[3] = pack2(f4.w, f4.w);
            const int base = h * 480 + m * 4 + q2;   // float2 index
            #pragma unroll
            for (int k2l = 0; k2l < 4; k2l++) {
                const float2 w2 = w2_sm[base + k2l * 120];
                const u64t wk = pack2(w2.x, w2.y);
                #pragma unroll
                for (int c = 0; c < 4; c++)
                    acc[k2l][c] = fma2(wk, fp[c], acc[k2l][c]);
            }
        }

        #pragma unroll
        for (int k2l = 0; k2l < 4; k2l++) {
            const int ke = h * 8 + k2l * 2;      // even k
            float lo[4], hi[4];
            #pragma unroll
            for (int c = 0; c < 4; c++) unpack2(acc[k2l][c], lo[c], hi[c]);

            {
                const size_t off = (size_t)n * BIGK2 + ke * KROW + q2 * QW + c17 * 4;
                __half2 p0 = __floats2half2_rn(lo[0], lo[1]);
                __half2 p1 = __floats2half2_rn(lo[2], lo[3]);
                uint2 pk;
                pk.x = *reinterpret_cast<uint32_t*>(&p0);
                pk.y = *reinterpret_cast<uint32_t*>(&p1);
                *reinterpret_cast<uint2*>(&g_A[off]) = pk;
            }
            if (ke + 1 < KP) {
                const size_t off = (size_t)n * BIGK2 + (ke + 1) * KROW + q2 * QW + c17 * 4;
                __half2 p0 = __floats2half2_rn(hi[0], hi[1]);
                __half2 p1 = __floats2half2_rn(hi[2], hi[3]);
                uint2 pk;
                pk.x = *reinterpret_cast<uint32_t*>(&p0);
                pk.y = *reinterpret_cast<uint32_t*>(&p1);
                *reinterpret_cast<uint2*>(&g_A[off]) = pk;
            }
        }
    }
}

// ---------------------------------------------------------------------------
// Stage 2: fp16 mma.sync GEMM. CTA 128x128, BK=48, 4 warps (64x64 tiles).
// ---------------------------------------------------------------------------
__global__ __launch_bounds__(128)
void gemm_mma_kernel(const float* __restrict__ bias, float* __restrict__ C)
{
    extern __shared__ __align__(16) char sm[];
    const uint32_t s0 = smem_u32(sm);

    const int tid  = threadIdx.x;
    const int wid  = tid >> 5;
    const int lane = tid & 31;
    const int r0   = blockIdx.x * BM;
    const int c0   = blockIdx.y * BN;

    const int wm = (wid & 1) * 64;
    const int wn = (wid >> 1) * 64;

    float acc[4][8][4];
    #pragma unroll
    for (int i = 0; i < 4; i++)
        #pragma unroll
        for (int j = 0; j < 8; j++)
            #pragma unroll
            for (int e = 0; e < 4; e++) acc[i][j][e] = 0.0f;

    auto load_chunk = [&](int c, int buf) {
        const int kc = c * BK;
        const uint32_t base = s0 + buf * BUF_BYTES;
        #pragma unroll
        for (int it = 0; it < 6; it++) {
            const int i   = tid + it * 128;          // 0..767
            const int row = i / 6;
            const int kq  = (i % 6) * 8;
            const uint32_t so = row * (LDS_ * 2) + kq * 2;
            cp16(base + so, &g_A[(size_t)(r0 + row) * BIGK2 + kc + kq]);
            cp16(base + MAT_BYTES + so, &g_B[(size_t)(c0 + row) * BIGK2 + kc + kq]);
        }
        cp_commit();
    };

    const int a_row = lane & 15;
    const int a_kof = (lane >> 4) * 8;
    const int b_nof = ((lane >> 4) * 8) + (lane & 7);
    const int b_kof = ((lane >> 3) & 1) * 8;

    load_chunk(0, 0);

    for (int c = 0; c < NKC; c++) {
        const int buf = c & 1;
        if (c + 1 < NKC) { load_chunk(c + 1, buf ^ 1); cp_wait1(); }
        else             { cp_wait0(); }
        __syncthreads();

        const uint32_t bA = s0 + buf * BUF_BYTES;
        const uint32_t bB = bA + MAT_BYTES;

        #pragma unroll
        for (int ks = 0; ks < 3; ks++) {
            const int k16 = ks * 16;
            uint32_t aH[4][4], bH[8][2];

            #pragma unroll
            for (int mt = 0; mt < 4; mt++) {
                const uint32_t off =
                    (wm + mt * 16 + a_row) * (LDS_ * 2) + (k16 + a_kof) * 2;
                ldmx4(bA + off, aH[mt]);
            }
            #pragma unroll
            for (int np = 0; np < 4; np++) {
                const uint32_t off =
                    (wn + np * 16 + b_nof) * (LDS_ * 2) + (k16 + b_kof) * 2;
                uint32_t t[4];
                ldmx4(bB + off, t);
                bH[np * 2 + 0][0] = t[0]; bH[np * 2 + 0][1] = t[1];
                bH[np * 2 + 1][0] = t[2]; bH[np * 2 + 1][1] = t[3];
            }

            #pragma unroll
            for (int mt = 0; mt < 4; mt++)
                #pragma unroll
                for (int nt = 0; nt < 8; nt++)
                    mma16816h(acc[mt][nt], aH[mt], bH[nt][0], bH[nt][1]);
        }
        __syncthreads();
    }

    const int erow = lane >> 2;
    const int ecol = (lane & 3) * 2;
    #pragma unroll
    for (int nt = 0; nt < 8; nt++) {
        const int col = c0 + wn + nt * 8 + ecol;
        const float b0 = bias[col], b1 = bias[col + 1];
        #pragma unroll
        for (int mt = 0; mt < 4; mt++) {
            #pragma unroll
            for (int h = 0; h < 2; h++) {
                const int row = r0 + wm + mt * 16 + erow + h * 8;
                if (row < N_Q) {
                    float v0 = acc[mt][nt][h * 2 + 0] + b0;
                    float v1 = acc[mt][nt][h * 2 + 1] + b1;
                    v0 = (v0 >= 0.f) ? v0 : 0.1f * v0;
                    v1 = (v1 >= 0.f) ? v1 : 0.1f * v1;
                    *reinterpret_cast<float2*>(&C[(size_t)row * COUT_ + col]) =
                        make_float2(v0, v1);
                }
            }
        }
    }
}

// ---------------------------------------------------------------------------
// Launch
// ---------------------------------------------------------------------------
extern "C" void kernel_launch(void* const* d_in, const int* in_sizes, int n_in,
                              void* d_out, int out_size) {
    const float* q_pts   = (const float*)d_in[0];
    const float* s_pts   = (const float*)d_in[1];
    const int*   inds    = (const int*)  d_in[2];
    const float* x       = (const float*)d_in[3];
    const float* q_lrf   = (const float*)d_in[4];
    const float* s_lrf   = (const float*)d_in[5];
    const float* kpts    = (const float*)d_in[6];
    const float* weights = (const float*)d_in[7];
    const float* W_lrf   = (const float*)d_in[8];
    const float* b_lrf   = (const float*)d_in[9];
    const float* bias    = (const float*)d_in[10];
    float* out = (float*)d_out;

    cudaFuncSetAttribute(bprep_kernel,
                         cudaFuncAttributeMaxDynamicSharedMemorySize, 65536);
    cudaFuncSetAttribute(gemm_mma_kernel,
                         cudaFuncAttributeMaxDynamicSharedMemorySize, SMEM_DYN);

    bprep_kernel<<<dim3(KP, 4, 2), 128, 65536>>>(weights, W_lrf, b_lrf);

    stage1_kernel<<<N_Q, 160>>>(q_pts, s_pts, inds, x, q_lrf, s_lrf, kpts);

    dim3 ggrid(M_PAD / BM, COUT_ / BN);
    gemm_mma_kernel<<<ggrid, 128, SMEM_DYN>>>(bias, out);
}

// round 10
// speedup vs baseline: 1.4071x; 1.0983x over previous
#include <cuda_runtime.h>
#include <cuda_fp16.h>
#include <cstdint>
#include <math.h>

// ---------------------------------------------------------------------------
// Problem constants
// ---------------------------------------------------------------------------
namespace {
constexpr int N_Q   = 20000;
constexpr int S_SUP = 20000;
constexpr int NEI   = 30;
constexpr int KP    = 15;
constexpr int CIN_  = 128;
constexpr int COUT_ = 256;
constexpr float INV_EXT = 20.0f;

constexpr int M_PAD = 20096;        // 157*128

// Extended-K layout: per k: 4 q-groups of 72 slots
//   j<32: x part; j in [32,68): 36 al channels; j=68: validity; j>68: pad
constexpr int QW    = 72;
constexpr int KROW  = 4 * QW;             // 288
constexpr int BIGK2 = KP * KROW;          // 4320

// GEMM tiling
constexpr int BM = 128, BN = 128, BK = 48;
constexpr int NKC = BIGK2 / BK;           // 90
constexpr int LDS_ = 56;                  // smem row stride (fp16 elems)
constexpr int MAT_BYTES = 128 * LDS_ * 2; // 14336
constexpr int BUF_BYTES = 2 * MAT_BYTES;  // A|B = 28672
constexpr int NSTAGE = 3;
constexpr int SMEM_DYN  = NSTAGE * BUF_BYTES;  // 86016, 3-stage pipeline
}

// ---------------------------------------------------------------------------
// Scratch (device globals, zero-initialized; pad rows never written)
// ---------------------------------------------------------------------------
__device__ __half g_A[(size_t)M_PAD * BIGK2];
__device__ __half g_B[(size_t)COUT_ * BIGK2];   // [co][kidx]

// ---------------------------------------------------------------------------
// PTX helpers (sm_80+/sm_100-family baseline; legal on family target)
// ---------------------------------------------------------------------------
__device__ __forceinline__ uint32_t smem_u32(const void* p) {
    uint32_t a;
    asm("{ .reg .u64 t; cvta.to.shared.u64 t, %1; cvt.u32.u64 %0, t; }"
        : "=r"(a) : "l"(p));
    return a;
}
__device__ __forceinline__ void cp16(uint32_t s, const void* g) {
    asm volatile("cp.async.cg.shared.global [%0], [%1], 16;" :: "r"(s), "l"(g));
}
// zero-fill variants: src_size = 0 -> no global read, smem zero-filled
__device__ __forceinline__ void cp16z(uint32_t s, const void* g, bool v) {
    const int sz = v ? 16 : 0;
    asm volatile("cp.async.cg.shared.global [%0], [%1], 16, %2;"
                 :: "r"(s), "l"(g), "r"(sz));
}
__device__ __forceinline__ void cp4z(uint32_t s, const void* g, bool v) {
    const int sz = v ? 4 : 0;
    asm volatile("cp.async.ca.shared.global [%0], [%1], 4, %2;"
                 :: "r"(s), "l"(g), "r"(sz));
}
__device__ __forceinline__ void cp_commit() {
    asm volatile("cp.async.commit_group;");
}
__device__ __forceinline__ void cp_wait2() {
    asm volatile("cp.async.wait_group 2;" ::: "memory");
}
__device__ __forceinline__ void cp_wait1() {
    asm volatile("cp.async.wait_group 1;" ::: "memory");
}
__device__ __forceinline__ void cp_wait0() {
    asm volatile("cp.async.wait_group 0;" ::: "memory");
}
__device__ __forceinline__ void ldmx4(uint32_t addr, uint32_t* r) {
    asm volatile("ldmatrix.sync.aligned.m8n8.x4.shared.b16 {%0,%1,%2,%3}, [%4];"
                 : "=r"(r[0]), "=r"(r[1]), "=r"(r[2]), "=r"(r[3]) : "r"(addr));
}
__device__ __forceinline__ void mma16816h(float* c, const uint32_t* a,
                                          uint32_t b0, uint32_t b1) {
    asm volatile(
        "mma.sync.aligned.m16n8k16.row.col.f32.f16.f16.f32 "
        "{%0,%1,%2,%3}, {%4,%5,%6,%7}, {%8,%9}, {%0,%1,%2,%3};"
        : "+f"(c[0]), "+f"(c[1]), "+f"(c[2]), "+f"(c[3])
        : "r"(a[0]), "r"(a[1]), "r"(a[2]), "r"(a[3]), "r"(b0), "r"(b1));
}
// packed fp32x2 (sm_100-family PTX; NOT an 'a'-suffix feature)
typedef unsigned long long u64t;
__device__ __forceinline__ u64t fma2(u64t a, u64t b, u64t c) {
    u64t d;
    asm("fma.rn.f32x2 %0, %1, %2, %3;" : "=l"(d) : "l"(a), "l"(b), "l"(c));
    return d;
}
__device__ __forceinline__ u64t pack2(float lo, float hi) {
    u64t d;
    asm("mov.b64 %0, {%1, %2};" : "=l"(d) : "f"(lo), "f"(hi));
    return d;
}
__device__ __forceinline__ void unpack2(u64t v, float& lo, float& hi) {
    asm("mov.b64 {%0, %1}, %2;" : "=f"(lo), "=f"(hi) : "l"(v));
}
__device__ __forceinline__ float sqrt_approx(float x) {
    float y;
    asm("sqrt.approx.f32 %0, %1;" : "=f"(y) : "f"(x));
    return y;
}

// ---------------------------------------------------------------------------
// B prep: g_B[co][k*288+q*72+j] from weights/W_lrf/b_lrf.
// ---------------------------------------------------------------------------
__global__ __launch_bounds__(128) void bprep_kernel(
    const float* __restrict__ W,       // [15][256][256]
    const float* __restrict__ W_lrf,   // [36][32]
    const float* __restrict__ b_lrf)   // [32]
{
    extern __shared__ float s[];       // [64][256]
    __shared__ float Wl[36 * 32];
    __shared__ float bl[32];

    const int k   = blockIdx.x;
    const int q   = blockIdx.y;
    const int co  = blockIdx.z * 128 + threadIdx.x;
    const int tid = threadIdx.x;

    for (int i = tid; i < 36 * 32; i += 128) Wl[i] = W_lrf[i];
    if (tid < 32) bl[tid] = b_lrf[tid];

    const float* Wb = W + ((size_t)k * 256 + q * 64) * 256;
    for (int i = tid; i < 64 * 256 / 4; i += 128) {
        reinterpret_cast<float4*>(s)[i] =
            reinterpret_cast<const float4*>(Wb)[i];
    }
    __syncthreads();

    float acc[37];
    #pragma unroll
    for (int t = 0; t < 37; t++) acc[t] = 0.0f;

    #pragma unroll 4
    for (int c = 0; c < 32; c++) {
        const float sv = s[(32 + c) * 256 + co];
        #pragma unroll
        for (int t = 0; t < 36; t++) acc[t] += Wl[t * 32 + c] * sv;
        acc[36] += bl[c] * sv;
    }

    __half h[72];
    #pragma unroll
    for (int j = 0; j < 32; j++) h[j] = __float2half_rn(s[j * 256 + co]);
    #pragma unroll
    for (int t = 0; t < 37; t++) h[32 + t] = __float2half_rn(acc[t]);
    h[69] = __float2half_rn(0.f); h[70] = h[69]; h[71] = h[69];

    __half* dst = &g_B[(size_t)co * BIGK2 + k * KROW + q * QW];
    #pragma unroll
    for (int v = 0; v < 9; v++)
        reinterpret_cast<uint4*>(dst)[v] = reinterpret_cast<const uint4*>(h)[v];
}

// ---------------------------------------------------------------------------
// Stage 1: cp.async-staged gather + geometry + f32x2 neighbor reduction.
// 160 threads/block, one block per query.
// ---------------------------------------------------------------------------
__global__ __launch_bounds__(160) void stage1_kernel(
    const float* __restrict__ q_pts,
    const float* __restrict__ s_pts,
    const int*   __restrict__ neighb_inds,
    const float* __restrict__ x,
    const float* __restrict__ q_lrf,
    const float* __restrict__ s_lrf,
    const float* __restrict__ kpts)
{
    __shared__ __align__(16) float ql[36];
    __shared__ __align__(16) float kp_s[48];
    __shared__ __align__(16) float2 w2_sm[8 * 30 * 4];  // [k2][m][q] k-pairs
    __shared__ __align__(16) float f_sm[30 * KROW];     // [m][q*72 + j]
    __shared__ __align__(16) float slrf_sm[30 * 36];    // [m][36]
    __shared__ __align__(16) float spts_sm[30 * 4];     // [m][xyz-]
    __shared__ int   ind_s[30];
    __shared__ float qp[3];

    const int n   = blockIdx.x;
    const int tid = threadIdx.x;

    if (tid < 36) ql[tid]    = q_lrf[(size_t)n * 36 + tid];
    if (tid < 45) kp_s[tid]  = kpts[tid];
    if (tid < 3)  qp[tid]    = q_pts[(size_t)n * 3 + tid];
    if (tid < 30) ind_s[tid] = neighb_inds[(size_t)n * NEI + tid];
    __syncthreads();   // ind_s ready for cp.async issue

    const uint32_t fb    = smem_u32(f_sm);
    const uint32_t slb   = smem_u32(slrf_sm);
    const uint32_t spb   = smem_u32(spts_sm);

    // ---- async gather: x rows into j<32 slots (960 x 16B) ----
    #pragma unroll
    for (int it = 0; it < 6; it++) {
        const int i = tid + it * 160;
        if (i < 960) {
            const int m   = i >> 5;        // /32
            const int q   = (i >> 3) & 3;
            const int c4  = i & 7;
            const int ind = ind_s[m];
            const bool v  = (ind < S_SUP);
            cp16z(fb + (m * KROW + q * QW + c4 * 4) * 4,
                  x + (size_t)(v ? ind : 0) * CIN_ + q * 32 + c4 * 4, v);
        }
    }
    // ---- async gather: s_lrf rows (270 x 16B) ----
    #pragma unroll
    for (int it = 0; it < 2; it++) {
        const int i = tid + it * 160;
        if (i < 270) {
            const int m = i / 9, t = i % 9;
            const int ind = ind_s[m];
            const bool v  = (ind < S_SUP);
            cp16z(slb + (m * 36 + t * 4) * 4,
                  s_lrf + (size_t)(v ? ind : 0) * 36 + t * 4, v);
        }
    }
    // ---- async gather: s_pts (3 x 4B per m; 12B stride only 4B-aligned) ----
    if (tid < 90) {
        const int m = tid / 3, e = tid % 3;
        const int ind = ind_s[m];
        const bool v  = (ind < S_SUP);
        cp4z(spb + (m * 4 + e) * 4, s_pts + (size_t)(v ? ind : 0) * 3 + e, v);
    }
    cp_commit();
    cp_wait0();
    __syncthreads();

    // ---- per-(m,q) geometry (reads staged smem only) ----
    if (tid < 120) {
        const int m = tid >> 2;
        const int q = tid & 3;
        const int ind = ind_s[m];
        const bool valid = (ind < S_SUP);
        const float* qlr = &ql[q * 9];

        const float nb0 = spts_sm[m * 4 + 0] - qp[0];
        const float nb1 = spts_sm[m * 4 + 1] - qp[1];
        const float nb2 = spts_sm[m * 4 + 2] - qp[2];
        const float a0 = nb0 * qlr[0] + nb1 * qlr[3] + nb2 * qlr[6];
        const float a1 = nb0 * qlr[1] + nb1 * qlr[4] + nb2 * qlr[7];
        const float a2 = nb0 * qlr[2] + nb1 * qlr[5] + nb2 * qlr[8];

        float wv[16];
        #pragma unroll
        for (int k = 0; k < KP; k++) {
            const float d0 = a0 - kp_s[k * 3 + 0];
            const float d1 = a1 - kp_s[k * 3 + 1];
            const float d2 = a2 - kp_s[k * 3 + 2];
            const float sq = d0 * d0 + d1 * d1 + d2 * d2;
            float w = 1.0f - sqrt_approx(sq) * INV_EXT;
            w = fmaxf(w, 0.0f);
            wv[k] = valid ? w : 0.0f;
        }
        wv[15] = 0.0f;
        #pragma unroll
        for (int k2 = 0; k2 < 8; k2++)
            w2_sm[(k2 * 30 + m) * 4 + q] = make_float2(wv[2 * k2], wv[2 * k2 + 1]);

        float sl[36];
        {
            const float4* p = reinterpret_cast<const float4*>(&slrf_sm[m * 36]);
            #pragma unroll
            for (int t = 0; t < 9; t++) {
                const float4 v = p[t];
                sl[t * 4 + 0] = v.x; sl[t * 4 + 1] = v.y;
                sl[t * 4 + 2] = v.z; sl[t * 4 + 3] = v.w;
            }
        }
        float* fr = &f_sm[m * KROW + q * QW];
        #pragma unroll
        for (int s = 0; s < 4; s++)
            #pragma unroll
            for (int i = 0; i < 3; i++)
                #pragma unroll
                for (int j = 0; j < 3; j++) {
                    fr[32 + s * 9 + i * 3 + j] =
                        qlr[0 * 3 + i] * sl[s * 9 + 0 * 3 + j] +
                        qlr[1 * 3 + i] * sl[s * 9 + 1 * 3 + j] +
                        qlr[2 * 3 + i] * sl[s * 9 + 2 * 3 + j];
                }
        fr[68] = valid ? 1.0f : 0.0f;
        fr[69] = 0.0f; fr[70] = 0.0f; fr[71] = 0.0f;
    }
    __syncthreads();

    // ---- phase 2 (f32x2): A[q,2k2+e,j] = sum_m w[q,k,m] * f[m,q,j] ----
    // 144 tasks on 160 threads: (h,q,c17); 4 k-pairs x 4 channels each.
    if (tid < 144) {
        const int c17 = tid % 18;
        const int rem = tid / 18;
        const int q2  = rem & 3;
        const int h   = rem >> 2;          // k2 base = h*4

        u64t acc[4][4];
        #pragma unroll
        for (int i = 0; i < 4; i++)
            #pragma unroll
            for (int j = 0; j < 4; j++) acc[i][j] = 0ull;

        #pragma unroll 1
        for (int m = 0; m < NEI; m++) {
            const float4 f4 = *reinterpret_cast<const float4*>(
                &f_sm[m * KROW + q2 * QW + c17 * 4]);
            u64t fp[4];
            fp[0] = pack2(f4.x, f4.x);
            fp[1] = pack2(f4.y, f4.y);
            fp[2] = pack2(f4.z, f4.z);
            fp[3] = pack2(f4.w, f4.w);
            const int base = h * 480 + m * 4 + q2;   // float2 index
            #pragma unroll
            for (int k2l = 0; k2l < 4; k2l++) {
                const float2 w2 = w2_sm[base + k2l * 120];
                const u64t wk = pack2(w2.x, w2.y);
                #pragma unroll
                for (int c = 0; c < 4; c++)
                    acc[k2l][c] = fma2(wk, fp[c], acc[k2l][c]);
            }
        }

        #pragma unroll
        for (int k2l = 0; k2l < 4; k2l++) {
            const int ke = h * 8 + k2l * 2;      // even k
            float lo[4], hi[4];
            #pragma unroll
            for (int c = 0; c < 4; c++) unpack2(acc[k2l][c], lo[c], hi[c]);

            {
                const size_t off = (size_t)n * BIGK2 + ke * KROW + q2 * QW + c17 * 4;
                __half2 p0 = __floats2half2_rn(lo[0], lo[1]);
                __half2 p1 = __floats2half2_rn(lo[2], lo[3]);
                uint2 pk;
                pk.x = *reinterpret_cast<uint32_t*>(&p0);
                pk.y = *reinterpret_cast<uint32_t*>(&p1);
                *reinterpret_cast<uint2*>(&g_A[off]) = pk;
            }
            if (ke + 1 < KP) {
                const size_t off = (size_t)n * BIGK2 + (ke + 1) * KROW + q2 * QW + c17 * 4;
                __half2 p0 = __floats2half2_rn(hi[0], hi[1]);
                __half2 p1 = __floats2half2_rn(hi[2], hi[3]);
                uint2 pk;
                pk.x = *reinterpret_cast<uint32_t*>(&p0);
                pk.y = *reinterpret_cast<uint32_t*>(&p1);
                *reinterpret_cast<uint2*>(&g_A[off]) = pk;
            }
        }
    }
}

// ---------------------------------------------------------------------------
// Stage 2: fp16 mma.sync GEMM. CTA 128x128, BK=48, 4 warps (64x64 tiles),
// 3-stage cp.async pipeline.
// ---------------------------------------------------------------------------
__global__ __launch_bounds__(128)
void gemm_mma_kernel(const float* __restrict__ bias, float* __restrict__ C)
{
    extern __shared__ __align__(16) char sm[];
    const uint32_t s0 = smem_u32(sm);

    const int tid  = threadIdx.x;
    const int wid  = tid >> 5;
    const int lane = tid & 31;
    const int r0   = blockIdx.x * BM;
    const int c0   = blockIdx.y * BN;

    const int wm = (wid & 1) * 64;
    const int wn = (wid >> 1) * 64;

    float acc[4][8][4];
    #pragma unroll
    for (int i = 0; i < 4; i++)
        #pragma unroll
        for (int j = 0; j < 8; j++)
            #pragma unroll
            for (int e = 0; e < 4; e++) acc[i][j][e] = 0.0f;

    auto load_chunk = [&](int c, int buf) {
        const int kc = c * BK;
        const uint32_t base = s0 + buf * BUF_BYTES;
        #pragma unroll
        for (int it = 0; it < 6; it++) {
            const int i   = tid + it * 128;          // 0..767
            const int row = i / 6;
            const int kq  = (i % 6) * 8;
            const uint32_t so = row * (LDS_ * 2) + kq * 2;
            cp16(base + so, &g_A[(size_t)(r0 + row) * BIGK2 + kc + kq]);
            cp16(base + MAT_BYTES + so, &g_B[(size_t)(c0 + row) * BIGK2 + kc + kq]);
        }
        cp_commit();
    };

    const int a_row = lane & 15;
    const int a_kof = (lane >> 4) * 8;
    const int b_nof = ((lane >> 4) * 8) + (lane & 7);
    const int b_kof = ((lane >> 3) & 1) * 8;

    load_chunk(0, 0);
    load_chunk(1, 1);

    for (int c = 0; c < NKC; c++) {
        const int buf = c % NSTAGE;
        if (c + 2 < NKC) { load_chunk(c + 2, (c + 2) % NSTAGE); cp_wait2(); }
        else if (c + 1 < NKC) { cp_wait1(); }
        else { cp_wait0(); }
        __syncthreads();

        const uint32_t bA = s0 + buf * BUF_BYTES;
        const uint32_t bB = bA + MAT_BYTES;

        #pragma unroll
        for (int ks = 0; ks < 3; ks++) {
            const int k16 = ks * 16;
            uint32_t aH[4][4], bH[8][2];

            #pragma unroll
            for (int mt = 0; mt < 4; mt++) {
                const uint32_t off =
                    (wm + mt * 16 + a_row) * (LDS_ * 2) + (k16 + a_kof) * 2;
                ldmx4(bA + off, aH[mt]);
            }
            #pragma unroll
            for (int np = 0; np < 4; np++) {
                const uint32_t off =
                    (wn + np * 16 + b_nof) * (LDS_ * 2) + (k16 + b_kof) * 2;
                uint32_t t[4];
                ldmx4(bB + off, t);
                bH[np * 2 + 0][0] = t[0]; bH[np * 2 + 0][1] = t[1];
                bH[np * 2 + 1][0] = t[2]; bH[np * 2 + 1][1] = t[3];
            }

            #pragma unroll
            for (int mt = 0; mt < 4; mt++)
                #pragma unroll
                for (int nt = 0; nt < 8; nt++)
                    mma16816h(acc[mt][nt], aH[mt], bH[nt][0], bH[nt][1]);
        }
        __syncthreads();
    }

    const int erow = lane >> 2;
    const int ecol = (lane & 3) * 2;
    #pragma unroll
    for (int nt = 0; nt < 8; nt++) {
        const int col = c0 + wn + nt * 8 + ecol;
        const float b0 = bias[col], b1 = bias[col + 1];
        #pragma unroll
        for (int mt = 0; mt < 4; mt++) {
            #pragma unroll
            for (int h = 0; h < 2; h++) {
                const int row = r0 + wm + mt * 16 + erow + h * 8;
                if (row < N_Q) {
                    float v0 = acc[mt][nt][h * 2 + 0] + b0;
                    float v1 = acc[mt][nt][h * 2 + 1] + b1;
                    v0 = (v0 >= 0.f) ? v0 : 0.1f * v0;
                    v1 = (v1 >= 0.f) ? v1 : 0.1f * v1;
                    *reinterpret_cast<float2*>(&C[(size_t)row * COUT_ + col]) =
                        make_float2(v0, v1);
                }
            }
        }
    }
}

// ---------------------------------------------------------------------------
// Launch
// ---------------------------------------------------------------------------
extern "C" void kernel_launch(void* const* d_in, const int* in_sizes, int n_in,
                              void* d_out, int out_size) {
    const float* q_pts   = (const float*)d_in[0];
    const float* s_pts   = (const float*)d_in[1];
    const int*   inds    = (const int*)  d_in[2];
    const float* x       = (const float*)d_in[3];
    const float* q_lrf   = (const float*)d_in[4];
    const float* s_lrf   = (const float*)d_in[5];
    const float* kpts    = (const float*)d_in[6];
    const float* weights = (const float*)d_in[7];
    const float* W_lrf   = (const float*)d_in[8];
    const float* b_lrf   = (const float*)d_in[9];
    const float* bias    = (const float*)d_in[10];
    float* out = (float*)d_out;

    cudaFuncSetAttribute(bprep_kernel,
                         cudaFuncAttributeMaxDynamicSharedMemorySize, 65536);
    cudaFuncSetAttribute(gemm_mma_kernel,
                         cudaFuncAttributeMaxDynamicSharedMemorySize, SMEM_DYN);

    bprep_kernel<<<dim3(KP, 4, 2), 128, 65536>>>(weights, W_lrf, b_lrf);

    stage1_kernel<<<N_Q, 160>>>(q_pts, s_pts, inds, x, q_lrf, s_lrf, kpts);

    dim3 ggrid(M_PAD / BM, COUT_ / BN);
    gemm_mma_kernel<<<ggrid, 128, SMEM_DYN>>>(bias, out);
}

// round 11
// speedup vs baseline: 1.5627x; 1.1106x over previous
#include <cuda_runtime.h>
#include <cuda_fp16.h>
#include <cstdint>
#include <math.h>

// ---------------------------------------------------------------------------
// Problem constants
// ---------------------------------------------------------------------------
namespace {
constexpr int N_Q   = 20000;
constexpr int S_SUP = 20000;
constexpr int NEI   = 30;
constexpr int KP    = 15;
constexpr int CIN_  = 128;
constexpr int COUT_ = 256;
constexpr float INV_EXT = 20.0f;

constexpr int M_PAD = 20096;        // 157*128

// Extended-K layout: per k: 4 q-groups of 72 slots
//   j<32: x part; j in [32,68): 36 al channels; j=68: validity; j>68: pad
constexpr int QW    = 72;
constexpr int KROW  = 4 * QW;             // 288
constexpr int BIGK2 = KP * KROW;          // 4320

// stage1 smem f layout row stride (halfs): 296 -> 20-word row offset, conflict-free
constexpr int LDF   = 296;
constexpr int LDW   = 40;                 // w_h row stride (halfs)

// GEMM tiling
constexpr int BM = 128, BN = 128, BK = 48;
constexpr int NKC = BIGK2 / BK;           // 90
constexpr int LDS_ = 56;                  // smem row stride (fp16 elems)
constexpr int MAT_BYTES = 128 * LDS_ * 2; // 14336
constexpr int BUF_BYTES = 2 * MAT_BYTES;  // A|B = 28672
constexpr int NSTAGE = 3;
constexpr int SMEM_DYN  = NSTAGE * BUF_BYTES;  // 86016, 3-stage pipeline
}

// ---------------------------------------------------------------------------
// Scratch (device globals, zero-initialized; pad rows never written)
// ---------------------------------------------------------------------------
__device__ __half g_A[(size_t)M_PAD * BIGK2];
__device__ __half g_B[(size_t)COUT_ * BIGK2];   // [co][kidx]

// ---------------------------------------------------------------------------
// PTX helpers (sm_80+/sm_100-family baseline; legal on family target)
// ---------------------------------------------------------------------------
__device__ __forceinline__ uint32_t smem_u32(const void* p) {
    uint32_t a;
    asm("{ .reg .u64 t; cvta.to.shared.u64 t, %1; cvt.u32.u64 %0, t; }"
        : "=r"(a) : "l"(p));
    return a;
}
__device__ __forceinline__ void cp16(uint32_t s, const void* g) {
    asm volatile("cp.async.cg.shared.global [%0], [%1], 16;" :: "r"(s), "l"(g));
}
__device__ __forceinline__ void cp16z(uint32_t s, const void* g, bool v) {
    const int sz = v ? 16 : 0;
    asm volatile("cp.async.cg.shared.global [%0], [%1], 16, %2;"
                 :: "r"(s), "l"(g), "r"(sz));
}
__device__ __forceinline__ void cp4z(uint32_t s, const void* g, bool v) {
    const int sz = v ? 4 : 0;
    asm volatile("cp.async.ca.shared.global [%0], [%1], 4, %2;"
                 :: "r"(s), "l"(g), "r"(sz));
}
__device__ __forceinline__ void cp_commit() {
    asm volatile("cp.async.commit_group;");
}
__device__ __forceinline__ void cp_wait2() {
    asm volatile("cp.async.wait_group 2;" ::: "memory");
}
__device__ __forceinline__ void cp_wait1() {
    asm volatile("cp.async.wait_group 1;" ::: "memory");
}
__device__ __forceinline__ void cp_wait0() {
    asm volatile("cp.async.wait_group 0;" ::: "memory");
}
__device__ __forceinline__ void ldmx4(uint32_t addr, uint32_t* r) {
    asm volatile("ldmatrix.sync.aligned.m8n8.x4.shared.b16 {%0,%1,%2,%3}, [%4];"
                 : "=r"(r[0]), "=r"(r[1]), "=r"(r[2]), "=r"(r[3]) : "r"(addr));
}
__device__ __forceinline__ void ldmx4t(uint32_t addr, uint32_t* r) {
    asm volatile("ldmatrix.sync.aligned.m8n8.x4.trans.shared.b16 {%0,%1,%2,%3}, [%4];"
                 : "=r"(r[0]), "=r"(r[1]), "=r"(r[2]), "=r"(r[3]) : "r"(addr));
}
__device__ __forceinline__ void ldmx2t(uint32_t addr, uint32_t* r) {
    asm volatile("ldmatrix.sync.aligned.m8n8.x2.trans.shared.b16 {%0,%1}, [%2];"
                 : "=r"(r[0]), "=r"(r[1]) : "r"(addr));
}
__device__ __forceinline__ void mma16816h(float* c, const uint32_t* a,
                                          uint32_t b0, uint32_t b1) {
    asm volatile(
        "mma.sync.aligned.m16n8k16.row.col.f32.f16.f16.f32 "
        "{%0,%1,%2,%3}, {%4,%5,%6,%7}, {%8,%9}, {%0,%1,%2,%3};"
        : "+f"(c[0]), "+f"(c[1]), "+f"(c[2]), "+f"(c[3])
        : "r"(a[0]), "r"(a[1]), "r"(a[2]), "r"(a[3]), "r"(b0), "r"(b1));
}
__device__ __forceinline__ float sqrt_approx(float x) {
    float y;
    asm("sqrt.approx.f32 %0, %1;" : "=f"(y) : "f"(x));
    return y;
}
__device__ __forceinline__ uint32_t h2pack(float a, float b) {
    const __half2 h = __floats2half2_rn(a, b);
    return *reinterpret_cast<const uint32_t*>(&h);
}

// ---------------------------------------------------------------------------
// B prep: g_B[co][k*288+q*72+j] from weights/W_lrf/b_lrf.
// ---------------------------------------------------------------------------
__global__ __launch_bounds__(128) void bprep_kernel(
    const float* __restrict__ W,       // [15][256][256]
    const float* __restrict__ W_lrf,   // [36][32]
    const float* __restrict__ b_lrf)   // [32]
{
    extern __shared__ float s[];       // [64][256]
    __shared__ float Wl[36 * 32];
    __shared__ float bl[32];

    const int k   = blockIdx.x;
    const int q   = blockIdx.y;
    const int co  = blockIdx.z * 128 + threadIdx.x;
    const int tid = threadIdx.x;

    for (int i = tid; i < 36 * 32; i += 128) Wl[i] = W_lrf[i];
    if (tid < 32) bl[tid] = b_lrf[tid];

    const float* Wb = W + ((size_t)k * 256 + q * 64) * 256;
    for (int i = tid; i < 64 * 256 / 4; i += 128) {
        reinterpret_cast<float4*>(s)[i] =
            reinterpret_cast<const float4*>(Wb)[i];
    }
    __syncthreads();

    float acc[37];
    #pragma unroll
    for (int t = 0; t < 37; t++) acc[t] = 0.0f;

    #pragma unroll 4
    for (int c = 0; c < 32; c++) {
        const float sv = s[(32 + c) * 256 + co];
        #pragma unroll
        for (int t = 0; t < 36; t++) acc[t] += Wl[t * 32 + c] * sv;
        acc[36] += bl[c] * sv;
    }

    __half h[72];
    #pragma unroll
    for (int j = 0; j < 32; j++) h[j] = __float2half_rn(s[j * 256 + co]);
    #pragma unroll
    for (int t = 0; t < 37; t++) h[32 + t] = __float2half_rn(acc[t]);
    h[69] = __float2half_rn(0.f); h[70] = h[69]; h[71] = h[69];

    __half* dst = &g_B[(size_t)co * BIGK2 + k * KROW + q * QW];
    #pragma unroll
    for (int v = 0; v < 9; v++)
        reinterpret_cast<uint4*>(dst)[v] = reinterpret_cast<const uint4*>(h)[v];
}

// ---------------------------------------------------------------------------
// Stage 1: cp.async gather + geometry + tensor-core neighbor reduction.
// 128 threads/block (4 warps, one per q in the MMA phase).
//   w_h [q][16 k][40] fp16 (stride 40 halfs = conflict-free ldmatrix)
//   f_h [32 m][296] fp16 (stride 296 halfs = conflict-free ldmatrix.trans)
//   per warp q: out[16 k, 72 j] = w[16,32m] @ f[32m, 72j]  (m16n8k16, fp32 acc)
// ---------------------------------------------------------------------------
__global__ __launch_bounds__(128) void stage1_kernel(
    const float* __restrict__ q_pts,
    const float* __restrict__ s_pts,
    const int*   __restrict__ neighb_inds,
    const float* __restrict__ x,
    const float* __restrict__ q_lrf,
    const float* __restrict__ s_lrf,
    const float* __restrict__ kpts)
{
    __shared__ __align__(16) float  xstage[30 * 128];   // 15360 B
    __shared__ __align__(16) __half f_h[32 * LDF];      // 18944 B
    __shared__ __align__(16) __half w_h[4 * 16 * LDW];  // 5120 B
    __shared__ __align__(16) float  slrf_sm[30 * 36];   // 4320 B
    __shared__ __align__(16) float  spts_sm[30 * 4];
    __shared__ float ql[36];
    __shared__ float kp_s[48];
    __shared__ int   ind_s[30];
    __shared__ float qp[3];

    const int n    = blockIdx.x;
    const int tid  = threadIdx.x;
    const int wid  = tid >> 5;
    const int lane = tid & 31;

    if (tid < 36) ql[tid]    = q_lrf[(size_t)n * 36 + tid];
    if (tid < 45) kp_s[tid]  = kpts[tid];
    if (tid < 3)  qp[tid]    = q_pts[(size_t)n * 3 + tid];
    if (tid < 30) ind_s[tid] = neighb_inds[(size_t)n * NEI + tid];
    __syncthreads();   // ind_s ready

    const uint32_t xb  = smem_u32(xstage);
    const uint32_t slb = smem_u32(slrf_sm);
    const uint32_t spb = smem_u32(spts_sm);
    const uint32_t fba = smem_u32(f_h);
    const uint32_t wba = smem_u32(w_h);

    // ---- async gather: x rows -> xstage[m][128] f32 (960 x 16B) ----
    #pragma unroll
    for (int it = 0; it < 8; it++) {
        const int i = tid + it * 128;
        if (i < 960) {
            const int m   = i >> 5;
            const int c16 = i & 31;
            const int ind = ind_s[m];
            const bool v  = (ind < S_SUP);
            cp16z(xb + m * 512 + c16 * 16,
                  x + (size_t)(v ? ind : 0) * CIN_ + c16 * 4, v);
        }
    }
    // ---- async gather: s_lrf rows (270 x 16B) ----
    #pragma unroll
    for (int it = 0; it < 3; it++) {
        const int i = tid + it * 128;
        if (i < 270) {
            const int m = i / 9, t = i % 9;
            const int ind = ind_s[m];
            const bool v  = (ind < S_SUP);
            cp16z(slb + (m * 36 + t * 4) * 4,
                  s_lrf + (size_t)(v ? ind : 0) * 36 + t * 4, v);
        }
    }
    // ---- async gather: s_pts (3 x 4B per m) ----
    if (tid < 90) {
        const int m = tid / 3, e = tid % 3;
        const int ind = ind_s[m];
        const bool v  = (ind < S_SUP);
        cp4z(spb + (m * 4 + e) * 4, s_pts + (size_t)(v ? ind : 0) * 3 + e, v);
    }
    cp_commit();

    // ---- zero w_h (all) and f_h pad rows m=30,31 while copies fly ----
    {
        uint4 z = make_uint4(0, 0, 0, 0);
        uint4* wz = reinterpret_cast<uint4*>(w_h);
        #pragma unroll
        for (int i = tid; i < 320; i += 128) wz[i] = z;      // 5120 B
        uint4* fz = reinterpret_cast<uint4*>(f_h + 30 * LDF);
        if (tid < 74) fz[tid] = z;                           // 2 rows
    }
    cp_wait0();
    __syncthreads();

    // ---- convert x part: xstage f32 -> f_h[m][q*72 + c] fp16 ----
    #pragma unroll
    for (int it = 0; it < 8; it++) {
        const int i = tid + it * 128;
        if (i < 960) {
            const int m   = i >> 5;
            const int c16 = i & 31;     // float4 index within 128 ch
            const int q   = c16 >> 3;
            const int c   = c16 & 7;
            const float4 v = *reinterpret_cast<const float4*>(&xstage[m * 128 + c16 * 4]);
            uint2 pk;
            pk.x = h2pack(v.x, v.y);
            pk.y = h2pack(v.z, v.w);
            *reinterpret_cast<uint2*>(&f_h[m * LDF + q * QW + c * 4]) = pk;
        }
    }

    // ---- per-(m,q) geometry -> w_h fp16 + f_h LRF channels fp16 ----
    if (tid < 120) {
        const int m = tid >> 2;
        const int q = tid & 3;
        const int ind = ind_s[m];
        const bool valid = (ind < S_SUP);
        const float* qlr = &ql[q * 9];

        const float nb0 = spts_sm[m * 4 + 0] - qp[0];
        const float nb1 = spts_sm[m * 4 + 1] - qp[1];
        const float nb2 = spts_sm[m * 4 + 2] - qp[2];
        const float a0 = nb0 * qlr[0] + nb1 * qlr[3] + nb2 * qlr[6];
        const float a1 = nb0 * qlr[1] + nb1 * qlr[4] + nb2 * qlr[7];
        const float a2 = nb0 * qlr[2] + nb1 * qlr[5] + nb2 * qlr[8];

        #pragma unroll
        for (int k = 0; k < KP; k++) {
            const float d0 = a0 - kp_s[k * 3 + 0];
            const float d1 = a1 - kp_s[k * 3 + 1];
            const float d2 = a2 - kp_s[k * 3 + 2];
            const float sq = d0 * d0 + d1 * d1 + d2 * d2;
            float w = 1.0f - sqrt_approx(sq) * INV_EXT;
            w = fmaxf(w, 0.0f);
            w_h[q * (16 * LDW) + k * LDW + m] = __float2half_rn(valid ? w : 0.0f);
        }
        // k=15 row already zeroed; m=30,31 columns zeroed.

        float sl[36];
        {
            const float4* p = reinterpret_cast<const float4*>(&slrf_sm[m * 36]);
            #pragma unroll
            for (int t = 0; t < 9; t++) {
                const float4 v = p[t];
                sl[t * 4 + 0] = v.x; sl[t * 4 + 1] = v.y;
                sl[t * 4 + 2] = v.z; sl[t * 4 + 3] = v.w;
            }
        }
        float alv[36];
        #pragma unroll
        for (int s = 0; s < 4; s++)
            #pragma unroll
            for (int i = 0; i < 3; i++)
                #pragma unroll
                for (int j = 0; j < 3; j++) {
                    alv[s * 9 + i * 3 + j] =
                        qlr[0 * 3 + i] * sl[s * 9 + 0 * 3 + j] +
                        qlr[1 * 3 + i] * sl[s * 9 + 1 * 3 + j] +
                        qlr[2 * 3 + i] * sl[s * 9 + 2 * 3 + j];
                }
        // pack 40 halfs: 36 al + validity + 3 zeros -> 5 x STS.128
        uint32_t pk[20];
        #pragma unroll
        for (int i = 0; i < 18; i++) pk[i] = h2pack(alv[2 * i], alv[2 * i + 1]);
        pk[18] = h2pack(valid ? 1.0f : 0.0f, 0.0f);
        pk[19] = 0u;
        uint4* dst = reinterpret_cast<uint4*>(&f_h[m * LDF + q * QW + 32]);
        #pragma unroll
        for (int v = 0; v < 5; v++) {
            uint4 u;
            u.x = pk[4 * v + 0]; u.y = pk[4 * v + 1];
            u.z = pk[4 * v + 2]; u.w = pk[4 * v + 3];
            dst[v] = u;
        }
    }
    __syncthreads();

    // ---- phase 2 (tensor cores): per warp q = wid ----
    {
        const int q = wid;
        float c[9][4];
        #pragma unroll
        for (int t = 0; t < 9; t++)
            #pragma unroll
            for (int e = 0; e < 4; e++) c[t][e] = 0.0f;

        const uint32_t wb = wba + q * (16 * LDW) * 2;
        // A (non-trans, proven pattern): row = lane&15, col half-sel
        const int a_row = lane & 15;
        const int a_kof = (lane >> 4) * 8;
        // B trans from [k][n]: row = k16 + (lane&7) + bit3*8 ; col = n0 + (lane>>4)*8
        const int b_row = (lane & 7) + ((lane >> 3) & 1) * 8;
        const int b_col = (lane >> 4) * 8;

        #pragma unroll
        for (int ks = 0; ks < 2; ks++) {
            const int k16 = ks * 16;
            uint32_t a[4];
            ldmx4(wb + (a_row * LDW + k16 + a_kof) * 2, a);

            uint32_t b[9][2];
            #pragma unroll
            for (int t = 0; t < 4; t++) {
                uint32_t r[4];
                ldmx4t(fba + ((k16 + b_row) * LDF + q * QW + t * 16 + b_col) * 2, r);
                b[2 * t + 0][0] = r[0]; b[2 * t + 0][1] = r[1];
                b[2 * t + 1][0] = r[2]; b[2 * t + 1][1] = r[3];
            }
            {
                uint32_t r[2];
                ldmx2t(fba + ((k16 + (lane & 15)) * LDF + q * QW + 64) * 2, r);
                b[8][0] = r[0]; b[8][1] = r[1];
            }

            #pragma unroll
            for (int t = 0; t < 9; t++)
                mma16816h(c[t], a, b[t][0], b[t][1]);
        }

        // ---- direct fp16 stores to g_A: rows k = r1, r1+8 (mask k=15) ----
        const int r1 = lane >> 2;
        const int jc = (lane & 3) * 2;
        __half* base = g_A + (size_t)n * BIGK2 + r1 * KROW + q * QW + jc;
        #pragma unroll
        for (int t = 0; t < 9; t++) {
            const __half2 lo = __floats2half2_rn(c[t][0], c[t][1]);
            *reinterpret_cast<__half2*>(base + t * 8) = lo;
        }
        if (r1 < 7) {
            __half* base2 = base + 8 * KROW;
            #pragma unroll
            for (int t = 0; t < 9; t++) {
                const __half2 hi = __floats2half2_rn(c[t][2], c[t][3]);
                *reinterpret_cast<__half2*>(base2 + t * 8) = hi;
            }
        }
    }
}

// ---------------------------------------------------------------------------
// Stage 2: fp16 mma.sync GEMM. CTA 128x128, BK=48, 4 warps (64x64 tiles),
// 3-stage cp.async pipeline. Grid (N-tiles, M-tiles) so the two CTAs of the
// same M row-tile are launch-adjacent -> A's second read hits L2.
// ---------------------------------------------------------------------------
__global__ __launch_bounds__(128)
void gemm_mma_kernel(const float* __restrict__ bias, float* __restrict__ C)
{
    extern __shared__ __align__(16) char sm[];
    const uint32_t s0 = smem_u32(sm);

    const int tid  = threadIdx.x;
    const int wid  = tid >> 5;
    const int lane = tid & 31;
    const int r0   = blockIdx.y * BM;
    const int c0   = blockIdx.x * BN;

    const int wm = (wid & 1) * 64;
    const int wn = (wid >> 1) * 64;

    float acc[4][8][4];
    #pragma unroll
    for (int i = 0; i < 4; i++)
        #pragma unroll
        for (int j = 0; j < 8; j++)
            #pragma unroll
            for (int e = 0; e < 4; e++) acc[i][j][e] = 0.0f;

    auto load_chunk = [&](int c, int buf) {
        const int kc = c * BK;
        const uint32_t base = s0 + buf * BUF_BYTES;
        #pragma unroll
        for (int it = 0; it < 6; it++) {
            const int i   = tid + it * 128;          // 0..767
            const int row = i / 6;
            const int kq  = (i % 6) * 8;
            const uint32_t so = row * (LDS_ * 2) + kq * 2;
            cp16(base + so, &g_A[(size_t)(r0 + row) * BIGK2 + kc + kq]);
            cp16(base + MAT_BYTES + so, &g_B[(size_t)(c0 + row) * BIGK2 + kc + kq]);
        }
        cp_commit();
    };

    const int a_row = lane & 15;
    const int a_kof = (lane >> 4) * 8;
    const int b_nof = ((lane >> 4) * 8) + (lane & 7);
    const int b_kof = ((lane >> 3) & 1) * 8;

    load_chunk(0, 0);
    load_chunk(1, 1);

    for (int c = 0; c < NKC; c++) {
        const int buf = c % NSTAGE;
        if (c + 2 < NKC) { load_chunk(c + 2, (c + 2) % NSTAGE); cp_wait2(); }
        else if (c + 1 < NKC) { cp_wait1(); }
        else { cp_wait0(); }
        __syncthreads();

        const uint32_t bA = s0 + buf * BUF_BYTES;
        const uint32_t bB = bA + MAT_BYTES;

        #pragma unroll
        for (int ks = 0; ks < 3; ks++) {
            const int k16 = ks * 16;
            uint32_t aH[4][4], bH[8][2];

            #pragma unroll
            for (int mt = 0; mt < 4; mt++) {
                const uint32_t off =
                    (wm + mt * 16 + a_row) * (LDS_ * 2) + (k16 + a_kof) * 2;
                ldmx4(bA + off, aH[mt]);
            }
            #pragma unroll
            for (int np = 0; np < 4; np++) {
                const uint32_t off =
                    (wn + np * 16 + b_nof) * (LDS_ * 2) + (k16 + b_kof) * 2;
                uint32_t t[4];
                ldmx4(bB + off, t);
                bH[np * 2 + 0][0] = t[0]; bH[np * 2 + 0][1] = t[1];
                bH[np * 2 + 1][0] = t[2]; bH[np * 2 + 1][1] = t[3];
            }

            #pragma unroll
            for (int mt = 0; mt < 4; mt++)
                #pragma unroll
                for (int nt = 0; nt < 8; nt++)
                    mma16816h(acc[mt][nt], aH[mt], bH[nt][0], bH[nt][1]);
        }
        __syncthreads();
    }

    const int erow = lane >> 2;
    const int ecol = (lane & 3) * 2;
    #pragma unroll
    for (int nt = 0; nt < 8; nt++) {
        const int col = c0 + wn + nt * 8 + ecol;
        const float b0 = bias[col], b1 = bias[col + 1];
        #pragma unroll
        for (int mt = 0; mt < 4; mt++) {
            #pragma unroll
            for (int h = 0; h < 2; h++) {
                const int row = r0 + wm + mt * 16 + erow + h * 8;
                if (row < N_Q) {
                    float v0 = acc[mt][nt][h * 2 + 0] + b0;
                    float v1 = acc[mt][nt][h * 2 + 1] + b1;
                    v0 = (v0 >= 0.f) ? v0 : 0.1f * v0;
                    v1 = (v1 >= 0.f) ? v1 : 0.1f * v1;
                    *reinterpret_cast<float2*>(&C[(size_t)row * COUT_ + col]) =
                        make_float2(v0, v1);
                }
            }
        }
    }
}

// ---------------------------------------------------------------------------
// Launch
// ---------------------------------------------------------------------------
extern "C" void kernel_launch(void* const* d_in, const int* in_sizes, int n_in,
                              void* d_out, int out_size) {
    const float* q_pts   = (const float*)d_in[0];
    const float* s_pts   = (const float*)d_in[1];
    const int*   inds    = (const int*)  d_in[2];
    const float* x       = (const float*)d_in[3];
    const float* q_lrf   = (const float*)d_in[4];
    const float* s_lrf   = (const float*)d_in[5];
    const float* kpts    = (const float*)d_in[6];
    const float* weights = (const float*)d_in[7];
    const float* W_lrf   = (const float*)d_in[8];
    const float* b_lrf   = (const float*)d_in[9];
    const float* bias    = (const float*)d_in[10];
    float* out = (float*)d_out;

    cudaFuncSetAttribute(bprep_kernel,
                         cudaFuncAttributeMaxDynamicSharedMemorySize, 65536);
    cudaFuncSetAttribute(gemm_mma_kernel,
                         cudaFuncAttributeMaxDynamicSharedMemorySize, SMEM_DYN);

    bprep_kernel<<<dim3(KP, 4, 2), 128, 65536>>>(weights, W_lrf, b_lrf);

    stage1_kernel<<<N_Q, 128>>>(q_pts, s_pts, inds, x, q_lrf, s_lrf, kpts);

    dim3 ggrid(COUT_ / BN, M_PAD / BM);
    gemm_mma_kernel<<<ggrid, 128, SMEM_DYN>>>(bias, out);
}

// round 12
// speedup vs baseline: 1.6371x; 1.0476x over previous
#include <cuda_runtime.h>
#include <cuda_fp16.h>
#include <cstdint>
#include <math.h>

// ---------------------------------------------------------------------------
// Problem constants
// ---------------------------------------------------------------------------
namespace {
constexpr int N_Q   = 20000;
constexpr int S_SUP = 20000;
constexpr int NEI   = 30;
constexpr int KP    = 15;
constexpr int CIN_  = 128;
constexpr int COUT_ = 256;
constexpr float INV_EXT = 20.0f;

constexpr int M_PAD = 20096;        // 157*128

// Extended-K layout: per k: 4 q-groups of 72 slots
constexpr int QW    = 72;
constexpr int KROW  = 4 * QW;             // 288
constexpr int BIGK2 = KP * KROW;          // 4320

// stage1 smem strides (halfs)
constexpr int LDF   = 296;   // f_h row stride: 20-word offset, conflict-free
constexpr int LDW   = 40;    // w_h row stride
constexpr int LDO   = 292;   // out_sm row stride: 18-word offset, conflict-free

// GEMM tiling
constexpr int BM = 128, BN = 128, BK = 48;
constexpr int NKC = BIGK2 / BK;           // 90
constexpr int LDS_ = 56;                  // smem row stride (fp16 elems)
constexpr int MAT_BYTES = 128 * LDS_ * 2; // 14336
constexpr int BUF_BYTES = 2 * MAT_BYTES;  // A|B = 28672
constexpr int NSTAGE = 3;
constexpr int SMEM_DYN  = NSTAGE * BUF_BYTES;  // 86016, 3-stage pipeline
}

// ---------------------------------------------------------------------------
// Scratch (device globals, zero-initialized; pad rows never written)
// ---------------------------------------------------------------------------
__device__ __half g_A[(size_t)M_PAD * BIGK2];
__device__ __half g_B[(size_t)COUT_ * BIGK2];   // [co][kidx]
__device__ __half g_xh[(size_t)S_SUP * CIN_];   // x pre-converted to fp16

// ---------------------------------------------------------------------------
// PTX helpers (sm_80+/sm_100-family baseline; legal on family target)
// ---------------------------------------------------------------------------
__device__ __forceinline__ uint32_t smem_u32(const void* p) {
    uint32_t a;
    asm("{ .reg .u64 t; cvta.to.shared.u64 t, %1; cvt.u32.u64 %0, t; }"
        : "=r"(a) : "l"(p));
    return a;
}
__device__ __forceinline__ void cp16(uint32_t s, const void* g) {
    asm volatile("cp.async.cg.shared.global [%0], [%1], 16;" :: "r"(s), "l"(g));
}
__device__ __forceinline__ void cp16z(uint32_t s, const void* g, bool v) {
    const int sz = v ? 16 : 0;
    asm volatile("cp.async.cg.shared.global [%0], [%1], 16, %2;"
                 :: "r"(s), "l"(g), "r"(sz));
}
__device__ __forceinline__ void cp4z(uint32_t s, const void* g, bool v) {
    const int sz = v ? 4 : 0;
    asm volatile("cp.async.ca.shared.global [%0], [%1], 4, %2;"
                 :: "r"(s), "l"(g), "r"(sz));
}
__device__ __forceinline__ void cp_commit() {
    asm volatile("cp.async.commit_group;");
}
__device__ __forceinline__ void cp_wait2() {
    asm volatile("cp.async.wait_group 2;" ::: "memory");
}
__device__ __forceinline__ void cp_wait1() {
    asm volatile("cp.async.wait_group 1;" ::: "memory");
}
__device__ __forceinline__ void cp_wait0() {
    asm volatile("cp.async.wait_group 0;" ::: "memory");
}
__device__ __forceinline__ void ldmx4(uint32_t addr, uint32_t* r) {
    asm volatile("ldmatrix.sync.aligned.m8n8.x4.shared.b16 {%0,%1,%2,%3}, [%4];"
                 : "=r"(r[0]), "=r"(r[1]), "=r"(r[2]), "=r"(r[3]) : "r"(addr));
}
__device__ __forceinline__ void ldmx4t(uint32_t addr, uint32_t* r) {
    asm volatile("ldmatrix.sync.aligned.m8n8.x4.trans.shared.b16 {%0,%1,%2,%3}, [%4];"
                 : "=r"(r[0]), "=r"(r[1]), "=r"(r[2]), "=r"(r[3]) : "r"(addr));
}
__device__ __forceinline__ void ldmx2t(uint32_t addr, uint32_t* r) {
    asm volatile("ldmatrix.sync.aligned.m8n8.x2.trans.shared.b16 {%0,%1}, [%2];"
                 : "=r"(r[0]), "=r"(r[1]) : "r"(addr));
}
__device__ __forceinline__ void mma16816h(float* c, const uint32_t* a,
                                          uint32_t b0, uint32_t b1) {
    asm volatile(
        "mma.sync.aligned.m16n8k16.row.col.f32.f16.f16.f32 "
        "{%0,%1,%2,%3}, {%4,%5,%6,%7}, {%8,%9}, {%0,%1,%2,%3};"
        : "+f"(c[0]), "+f"(c[1]), "+f"(c[2]), "+f"(c[3])
        : "r"(a[0]), "r"(a[1]), "r"(a[2]), "r"(a[3]), "r"(b0), "r"(b1));
}
__device__ __forceinline__ float sqrt_approx(float x) {
    float y;
    asm("sqrt.approx.f32 %0, %1;" : "=f"(y) : "f"(x));
    return y;
}
__device__ __forceinline__ uint32_t h2pack(float a, float b) {
    const __half2 h = __floats2half2_rn(a, b);
    return *reinterpret_cast<const uint32_t*>(&h);
}

// ---------------------------------------------------------------------------
// x -> fp16 pre-convert (same __float2half_rn rounding as before; bit-identical)
// ---------------------------------------------------------------------------
__global__ __launch_bounds__(256) void xhalf_kernel(const float* __restrict__ x) {
    const size_t i = (size_t)blockIdx.x * 1024 + threadIdx.x * 4;
    const float4 v = *reinterpret_cast<const float4*>(x + i);
    uint2 pk;
    pk.x = h2pack(v.x, v.y);
    pk.y = h2pack(v.z, v.w);
    *reinterpret_cast<uint2*>(&g_xh[i]) = pk;
}

// ---------------------------------------------------------------------------
// B prep: g_B[co][k*288+q*72+j] from weights/W_lrf/b_lrf.
// ---------------------------------------------------------------------------
__global__ __launch_bounds__(128) void bprep_kernel(
    const float* __restrict__ W,       // [15][256][256]
    const float* __restrict__ W_lrf,   // [36][32]
    const float* __restrict__ b_lrf)   // [32]
{
    extern __shared__ float s[];       // [64][256]
    __shared__ float Wl[36 * 32];
    __shared__ float bl[32];

    const int k   = blockIdx.x;
    const int q   = blockIdx.y;
    const int co  = blockIdx.z * 128 + threadIdx.x;
    const int tid = threadIdx.x;

    for (int i = tid; i < 36 * 32; i += 128) Wl[i] = W_lrf[i];
    if (tid < 32) bl[tid] = b_lrf[tid];

    const float* Wb = W + ((size_t)k * 256 + q * 64) * 256;
    for (int i = tid; i < 64 * 256 / 4; i += 128) {
        reinterpret_cast<float4*>(s)[i] =
            reinterpret_cast<const float4*>(Wb)[i];
    }
    __syncthreads();

    float acc[37];
    #pragma unroll
    for (int t = 0; t < 37; t++) acc[t] = 0.0f;

    #pragma unroll 4
    for (int c = 0; c < 32; c++) {
        const float sv = s[(32 + c) * 256 + co];
        #pragma unroll
        for (int t = 0; t < 36; t++) acc[t] += Wl[t * 32 + c] * sv;
        acc[36] += bl[c] * sv;
    }

    __half h[72];
    #pragma unroll
    for (int j = 0; j < 32; j++) h[j] = __float2half_rn(s[j * 256 + co]);
    #pragma unroll
    for (int t = 0; t < 37; t++) h[32 + t] = __float2half_rn(acc[t]);
    h[69] = __float2half_rn(0.f); h[70] = h[69]; h[71] = h[69];

    __half* dst = &g_B[(size_t)co * BIGK2 + k * KROW + q * QW];
    #pragma unroll
    for (int v = 0; v < 9; v++)
        reinterpret_cast<uint4*>(dst)[v] = reinterpret_cast<const uint4*>(h)[v];
}

// ---------------------------------------------------------------------------
// Stage 1: fp16 cp.async gather + geometry + tensor-core neighbor reduction.
// 128 threads/block (4 warps, one per q in the MMA phase).
// ---------------------------------------------------------------------------
__global__ __launch_bounds__(128) void stage1_kernel(
    const float* __restrict__ q_pts,
    const float* __restrict__ s_pts,
    const int*   __restrict__ neighb_inds,
    const float* __restrict__ q_lrf,
    const float* __restrict__ s_lrf,
    const float* __restrict__ kpts)
{
    __shared__ __align__(16) __half f_h[32 * LDF];      // 18944 B
    __shared__ __align__(16) __half w_h[4 * 16 * LDW];  // 5120 B
    __shared__ __align__(16) __half out_sm[15 * LDO];   // 8760 B
    __shared__ __align__(16) float  slrf_sm[30 * 36];   // 4320 B
    __shared__ __align__(16) float  spts_sm[30 * 4];
    __shared__ float ql[36];
    __shared__ float kp_s[48];
    __shared__ int   ind_s[30];
    __shared__ float qp[3];

    const int n    = blockIdx.x;
    const int tid  = threadIdx.x;
    const int wid  = tid >> 5;
    const int lane = tid & 31;

    if (tid < 36) ql[tid]    = q_lrf[(size_t)n * 36 + tid];
    if (tid < 45) kp_s[tid]  = kpts[tid];
    if (tid < 3)  qp[tid]    = q_pts[(size_t)n * 3 + tid];
    if (tid < 30) ind_s[tid] = neighb_inds[(size_t)n * NEI + tid];
    __syncthreads();   // ind_s ready

    const uint32_t slb = smem_u32(slrf_sm);
    const uint32_t spb = smem_u32(spts_sm);
    const uint32_t fba = smem_u32(f_h);
    const uint32_t wba = smem_u32(w_h);

    // ---- async gather: xh rows -> f_h[m][q*72 + c] fp16 (480 x 16B) ----
    #pragma unroll
    for (int it = 0; it < 4; it++) {
        const int i = tid + it * 128;
        if (i < 480) {
            const int m   = i >> 4;        // /16
            const int q   = (i >> 2) & 3;
            const int c8  = i & 3;         // 8-half chunk
            const int ind = ind_s[m];
            const bool v  = (ind < S_SUP);
            cp16z(fba + (m * LDF + q * QW + c8 * 8) * 2,
                  g_xh + (size_t)(v ? ind : 0) * CIN_ + q * 32 + c8 * 8, v);
        }
    }
    // ---- async gather: s_lrf rows (270 x 16B) ----
    #pragma unroll
    for (int it = 0; it < 3; it++) {
        const int i = tid + it * 128;
        if (i < 270) {
            const int m = i / 9, t = i % 9;
            const int ind = ind_s[m];
            const bool v  = (ind < S_SUP);
            cp16z(slb + (m * 36 + t * 4) * 4,
                  s_lrf + (size_t)(v ? ind : 0) * 36 + t * 4, v);
        }
    }
    // ---- async gather: s_pts (3 x 4B per m) ----
    if (tid < 90) {
        const int m = tid / 3, e = tid % 3;
        const int ind = ind_s[m];
        const bool v  = (ind < S_SUP);
        cp4z(spb + (m * 4 + e) * 4, s_pts + (size_t)(v ? ind : 0) * 3 + e, v);
    }
    cp_commit();

    // ---- zero w_h and f_h pad rows m=30,31 while copies fly ----
    {
        uint4 z = make_uint4(0, 0, 0, 0);
        uint4* wz = reinterpret_cast<uint4*>(w_h);
        #pragma unroll
        for (int i = tid; i < 320; i += 128) wz[i] = z;      // 5120 B
        uint4* fz = reinterpret_cast<uint4*>(f_h + 30 * LDF);
        if (tid < 74) fz[tid] = z;                           // 2 rows
    }
    cp_wait0();
    __syncthreads();

    // ---- per-(m,q) geometry -> w_h fp16 + f_h LRF channels fp16 ----
    if (tid < 120) {
        const int m = tid >> 2;
        const int q = tid & 3;
        const int ind = ind_s[m];
        const bool valid = (ind < S_SUP);
        const float* qlr = &ql[q * 9];

        const float nb0 = spts_sm[m * 4 + 0] - qp[0];
        const float nb1 = spts_sm[m * 4 + 1] - qp[1];
        const float nb2 = spts_sm[m * 4 + 2] - qp[2];
        const float a0 = nb0 * qlr[0] + nb1 * qlr[3] + nb2 * qlr[6];
        const float a1 = nb0 * qlr[1] + nb1 * qlr[4] + nb2 * qlr[7];
        const float a2 = nb0 * qlr[2] + nb1 * qlr[5] + nb2 * qlr[8];

        #pragma unroll
        for (int k = 0; k < KP; k++) {
            const float d0 = a0 - kp_s[k * 3 + 0];
            const float d1 = a1 - kp_s[k * 3 + 1];
            const float d2 = a2 - kp_s[k * 3 + 2];
            const float sq = d0 * d0 + d1 * d1 + d2 * d2;
            float w = 1.0f - sqrt_approx(sq) * INV_EXT;
            w = fmaxf(w, 0.0f);
            w_h[q * (16 * LDW) + k * LDW + m] = __float2half_rn(valid ? w : 0.0f);
        }

        float sl[36];
        {
            const float4* p = reinterpret_cast<const float4*>(&slrf_sm[m * 36]);
            #pragma unroll
            for (int t = 0; t < 9; t++) {
                const float4 v = p[t];
                sl[t * 4 + 0] = v.x; sl[t * 4 + 1] = v.y;
                sl[t * 4 + 2] = v.z; sl[t * 4 + 3] = v.w;
            }
        }
        float alv[36];
        #pragma unroll
        for (int s = 0; s < 4; s++)
            #pragma unroll
            for (int i = 0; i < 3; i++)
                #pragma unroll
                for (int j = 0; j < 3; j++) {
                    alv[s * 9 + i * 3 + j] =
                        qlr[0 * 3 + i] * sl[s * 9 + 0 * 3 + j] +
                        qlr[1 * 3 + i] * sl[s * 9 + 1 * 3 + j] +
                        qlr[2 * 3 + i] * sl[s * 9 + 2 * 3 + j];
                }
        uint32_t pk[20];
        #pragma unroll
        for (int i = 0; i < 18; i++) pk[i] = h2pack(alv[2 * i], alv[2 * i + 1]);
        pk[18] = h2pack(valid ? 1.0f : 0.0f, 0.0f);
        pk[19] = 0u;
        uint4* dst = reinterpret_cast<uint4*>(&f_h[m * LDF + q * QW + 32]);
        #pragma unroll
        for (int v = 0; v < 5; v++) {
            uint4 u;
            u.x = pk[4 * v + 0]; u.y = pk[4 * v + 1];
            u.z = pk[4 * v + 2]; u.w = pk[4 * v + 3];
            dst[v] = u;
        }
    }
    __syncthreads();

    // ---- phase 2 (tensor cores): per warp q = wid ----
    {
        const int q = wid;
        float c[9][4];
        #pragma unroll
        for (int t = 0; t < 9; t++)
            #pragma unroll
            for (int e = 0; e < 4; e++) c[t][e] = 0.0f;

        const uint32_t wb = wba + q * (16 * LDW) * 2;
        const int a_row = lane & 15;
        const int a_kof = (lane >> 4) * 8;
        const int b_row = (lane & 7) + ((lane >> 3) & 1) * 8;
        const int b_col = (lane >> 4) * 8;

        #pragma unroll
        for (int ks = 0; ks < 2; ks++) {
            const int k16 = ks * 16;
            uint32_t a[4];
            ldmx4(wb + (a_row * LDW + k16 + a_kof) * 2, a);

            uint32_t b[9][2];
            #pragma unroll
            for (int t = 0; t < 4; t++) {
                uint32_t r[4];
                ldmx4t(fba + ((k16 + b_row) * LDF + q * QW + t * 16 + b_col) * 2, r);
                b[2 * t + 0][0] = r[0]; b[2 * t + 0][1] = r[1];
                b[2 * t + 1][0] = r[2]; b[2 * t + 1][1] = r[3];
            }
            {
                uint32_t r[2];
                ldmx2t(fba + ((k16 + (lane & 15)) * LDF + q * QW + 64) * 2, r);
                b[8][0] = r[0]; b[8][1] = r[1];
            }

            #pragma unroll
            for (int t = 0; t < 9; t++)
                mma16816h(c[t], a, b[t][0], b[t][1]);
        }

        // ---- stage to out_sm [k][LDO] (conflict-free), mask k=15 ----
        const int r1 = lane >> 2;
        const int jc = (lane & 3) * 2;
        __half* base = out_sm + r1 * LDO + q * QW + jc;
        #pragma unroll
        for (int t = 0; t < 9; t++) {
            const __half2 lo = __floats2half2_rn(c[t][0], c[t][1]);
            *reinterpret_cast<__half2*>(base + t * 8) = lo;
        }
        if (r1 < 7) {
            __half* base2 = base + 8 * LDO;
            #pragma unroll
            for (int t = 0; t < 9; t++) {
                const __half2 hi = __floats2half2_rn(c[t][2], c[t][3]);
                *reinterpret_cast<__half2*>(base2 + t * 8) = hi;
            }
        }
    }
    __syncthreads();

    // ---- coalesced copy out_sm -> g_A (1080 x uint2) ----
    {
        __half* dst = g_A + (size_t)n * BIGK2;
        #pragma unroll 3
        for (int i = tid; i < 15 * 72; i += 128) {
            const int k  = i / 72;
            const int jj = i % 72;
            const uint2 v = *reinterpret_cast<const uint2*>(&out_sm[k * LDO + jj * 4]);
            *reinterpret_cast<uint2*>(dst + k * KROW + jj * 4) = v;
        }
    }
}

// ---------------------------------------------------------------------------
// Stage 2: fp16 mma.sync GEMM. CTA 128x128, BK=48, 4 warps (64x64 tiles),
// 3-stage cp.async pipeline. Grid (N-tiles, M-tiles).
// ---------------------------------------------------------------------------
__global__ __launch_bounds__(128)
void gemm_mma_kernel(const float* __restrict__ bias, float* __restrict__ C)
{
    extern __shared__ __align__(16) char sm[];
    const uint32_t s0 = smem_u32(sm);

    const int tid  = threadIdx.x;
    const int wid  = tid >> 5;
    const int lane = tid & 31;
    const int r0   = blockIdx.y * BM;
    const int c0   = blockIdx.x * BN;

    const int wm = (wid & 1) * 64;
    const int wn = (wid >> 1) * 64;

    float acc[4][8][4];
    #pragma unroll
    for (int i = 0; i < 4; i++)
        #pragma unroll
        for (int j = 0; j < 8; j++)
            #pragma unroll
            for (int e = 0; e < 4; e++) acc[i][j][e] = 0.0f;

    auto load_chunk = [&](int c, int buf) {
        const int kc = c * BK;
        const uint32_t base = s0 + buf * BUF_BYTES;
        #pragma unroll
        for (int it = 0; it < 6; it++) {
            const int i   = tid + it * 128;          // 0..767
            const int row = i / 6;
            const int kq  = (i % 6) * 8;
            const uint32_t so = row * (LDS_ * 2) + kq * 2;
            cp16(base + so, &g_A[(size_t)(r0 + row) * BIGK2 + kc + kq]);
            cp16(base + MAT_BYTES + so, &g_B[(size_t)(c0 + row) * BIGK2 + kc + kq]);
        }
        cp_commit();
    };

    const int a_row = lane & 15;
    const int a_kof = (lane >> 4) * 8;
    const int b_nof = ((lane >> 4) * 8) + (lane & 7);
    const int b_kof = ((lane >> 3) & 1) * 8;

    load_chunk(0, 0);
    load_chunk(1, 1);

    for (int c = 0; c < NKC; c++) {
        const int buf = c % NSTAGE;
        if (c + 2 < NKC) { load_chunk(c + 2, (c + 2) % NSTAGE); cp_wait2(); }
        else if (c + 1 < NKC) { cp_wait1(); }
        else { cp_wait0(); }
        __syncthreads();

        const uint32_t bA = s0 + buf * BUF_BYTES;
        const uint32_t bB = bA + MAT_BYTES;

        #pragma unroll
        for (int ks = 0; ks < 3; ks++) {
            const int k16 = ks * 16;
            uint32_t aH[4][4], bH[8][2];

            #pragma unroll
            for (int mt = 0; mt < 4; mt++) {
                const uint32_t off =
                    (wm + mt * 16 + a_row) * (LDS_ * 2) + (k16 + a_kof) * 2;
                ldmx4(bA + off, aH[mt]);
            }
            #pragma unroll
            for (int np = 0; np < 4; np++) {
                const uint32_t off =
                    (wn + np * 16 + b_nof) * (LDS_ * 2) + (k16 + b_kof) * 2;
                uint32_t t[4];
                ldmx4(bB + off, t);
                bH[np * 2 + 0][0] = t[0]; bH[np * 2 + 0][1] = t[1];
                bH[np * 2 + 1][0] = t[2]; bH[np * 2 + 1][1] = t[3];
            }

            #pragma unroll
            for (int mt = 0; mt < 4; mt++)
                #pragma unroll
                for (int nt = 0; nt < 8; nt++)
                    mma16816h(acc[mt][nt], aH[mt], bH[nt][0], bH[nt][1]);
        }
        __syncthreads();
    }

    const int erow = lane >> 2;
    const int ecol = (lane & 3) * 2;
    #pragma unroll
    for (int nt = 0; nt < 8; nt++) {
        const int col = c0 + wn + nt * 8 + ecol;
        const float b0 = bias[col], b1 = bias[col + 1];
        #pragma unroll
        for (int mt = 0; mt < 4; mt++) {
            #pragma unroll
            for (int h = 0; h < 2; h++) {
                const int row = r0 + wm + mt * 16 + erow + h * 8;
                if (row < N_Q) {
                    float v0 = acc[mt][nt][h * 2 + 0] + b0;
                    float v1 = acc[mt][nt][h * 2 + 1] + b1;
                    v0 = (v0 >= 0.f) ? v0 : 0.1f * v0;
                    v1 = (v1 >= 0.f) ? v1 : 0.1f * v1;
                    *reinterpret_cast<float2*>(&C[(size_t)row * COUT_ + col]) =
                        make_float2(v0, v1);
                }
            }
        }
    }
}

// ---------------------------------------------------------------------------
// Launch
// ---------------------------------------------------------------------------
extern "C" void kernel_launch(void* const* d_in, const int* in_sizes, int n_in,
                              void* d_out, int out_size) {
    const float* q_pts   = (const float*)d_in[0];
    const float* s_pts   = (const float*)d_in[1];
    const int*   inds    = (const int*)  d_in[2];
    const float* x       = (const float*)d_in[3];
    const float* q_lrf   = (const float*)d_in[4];
    const float* s_lrf   = (const float*)d_in[5];
    const float* kpts    = (const float*)d_in[6];
    const float* weights = (const float*)d_in[7];
    const float* W_lrf   = (const float*)d_in[8];
    const float* b_lrf   = (const float*)d_in[9];
    const float* bias    = (const float*)d_in[10];
    float* out = (float*)d_out;

    cudaFuncSetAttribute(bprep_kernel,
                         cudaFuncAttributeMaxDynamicSharedMemorySize, 65536);
    cudaFuncSetAttribute(gemm_mma_kernel,
                         cudaFuncAttributeMaxDynamicSharedMemorySize, SMEM_DYN);

    xhalf_kernel<<<(S_SUP * CIN_) / 1024, 256>>>(x);
    bprep_kernel<<<dim3(KP, 4, 2), 128, 65536>>>(weights, W_lrf, b_lrf);

    stage1_kernel<<<N_Q, 128>>>(q_pts, s_pts, inds, q_lrf, s_lrf, kpts);

    dim3 ggrid(COUT_ / BN, M_PAD / BM);
    gemm_mma_kernel<<<ggrid, 128, SMEM_DYN>>>(bias, out);
}